// round 1
// baseline (speedup 1.0000x reference)
#include <cuda_runtime.h>
#include <cuda_bf16.h>
#include <math.h>

// ---------------------------------------------------------------------------
// Problem constants (fixed shapes from reference: B=2, L=1024, d_model=1024,
// d_state=16, d_conv=4, d_inner=2048)
// ---------------------------------------------------------------------------
#define BATCH    2
#define LSEQ     1024
#define DMODEL   1024
#define DSTATE   16
#define DCONV    4
#define DINNER   2048
#define ROWS     (BATCH * LSEQ)          // 2048 token rows

// ---------------------------------------------------------------------------
// Scratch (device globals; no allocation allowed)
// ---------------------------------------------------------------------------
__device__ float g_xn   [ROWS * DMODEL];        // layernormed input          8 MB
__device__ float g_xz   [ROWS * 2 * DINNER];    // in_proj output            32 MB
__device__ float g_xc   [ROWS * DINNER];        // conv+silu output          16 MB
__device__ float g_bc   [ROWS * 2 * DSTATE];    // B|C projections          256 KB
__device__ float g_delta[ROWS * DINNER];        // clipped softplus dt       16 MB
__device__ float g_y    [ROWS * DINNER];        // gated scan output         16 MB
__device__ float g_out  [ROWS * DMODEL];        // out_proj + residual        8 MB

// ---------------------------------------------------------------------------
// LayerNorm (std with ddof=1, eps added to std, not var)
// ---------------------------------------------------------------------------
__device__ __forceinline__ float warp_sum32(float v) {
    #pragma unroll
    for (int m = 16; m > 0; m >>= 1) v += __shfl_xor_sync(0xffffffffu, v, m);
    return v;
}

__global__ void ln_kernel(const float* __restrict__ X,
                          const float* __restrict__ alpha,
                          const float* __restrict__ beta,
                          float* __restrict__ Y) {
    __shared__ float sh[2][8];
    int row = blockIdx.x;
    int tid = threadIdx.x;                           // 256 threads, 4 elems each
    const float* xr = X + (long)row * DMODEL;
    float4 xv = *(const float4*)(xr + tid * 4);
    float s  = xv.x + xv.y + xv.z + xv.w;
    float ss = xv.x*xv.x + xv.y*xv.y + xv.z*xv.z + xv.w*xv.w;
    s  = warp_sum32(s);
    ss = warp_sum32(ss);
    if ((tid & 31) == 0) { sh[0][tid >> 5] = s; sh[1][tid >> 5] = ss; }
    __syncthreads();
    float S = 0.f, SS = 0.f;
    #pragma unroll
    for (int w = 0; w < 8; ++w) { S += sh[0][w]; SS += sh[1][w]; }
    float mean = S * (1.0f / (float)DMODEL);
    float var  = fmaxf((SS - (float)DMODEL * mean * mean) * (1.0f / (float)(DMODEL - 1)), 0.f);
    float inv  = 1.0f / (sqrtf(var) + 1e-6f);
    float4 av = *(const float4*)(alpha + tid * 4);
    float4 bv = *(const float4*)(beta  + tid * 4);
    float4 o;
    o.x = av.x * (xv.x - mean) * inv + bv.x;
    o.y = av.y * (xv.y - mean) * inv + bv.y;
    o.z = av.z * (xv.z - mean) * inv + bv.z;
    o.w = av.w * (xv.w - mean) * inv + bv.w;
    *(float4*)(Y + (long)row * DMODEL + tid * 4) = o;
}

// ---------------------------------------------------------------------------
// Tiled fp32 GEMM: C[M,N] = A[M,K] * B[N,K]^T (+bias, + optional epilogue)
// BM=BN=128, BK=16, 256 threads, 8x8 per thread.
// EPI: 0 = bias only, 1 = clip(softplus(v),1e-4,10), 2 = bias + residual
// ---------------------------------------------------------------------------
#define EPI_BIAS     0
#define EPI_SOFTPLUS 1
#define EPI_RESID    2

template<int EPI>
__global__ __launch_bounds__(256, 2)
void gemm_nt(const float* __restrict__ A, const float* __restrict__ B,
             const float* __restrict__ bias, const float* __restrict__ resid,
             float* __restrict__ C, int M, int N, int K) {
    __shared__ float As[16][132];
    __shared__ float Bs[16][132];
    int bm = blockIdx.y * 128;
    int bn = blockIdx.x * 128;
    int tid = threadIdx.x;
    int tx = tid & 15;              // output col group
    int ty = tid >> 4;              // output row group
    int lr = tid >> 2;              // load row 0..63
    int lc = (tid & 3) * 4;         // load col (float4)

    const float* Ap = A + (long)(bm + lr) * K + lc;
    const float* Bp = B + (long)(bn + lr) * K + lc;

    float acc[8][8];
    #pragma unroll
    for (int i = 0; i < 8; ++i)
        #pragma unroll
        for (int j = 0; j < 8; ++j) acc[i][j] = 0.f;

    for (int k0 = 0; k0 < K; k0 += 16) {
        #pragma unroll
        for (int r = 0; r < 2; ++r) {
            float4 av = *(const float4*)(Ap + (long)(r * 64) * K + k0);
            float4 bv = *(const float4*)(Bp + (long)(r * 64) * K + k0);
            int m = lr + r * 64;
            As[lc + 0][m] = av.x; As[lc + 1][m] = av.y;
            As[lc + 2][m] = av.z; As[lc + 3][m] = av.w;
            Bs[lc + 0][m] = bv.x; Bs[lc + 1][m] = bv.y;
            Bs[lc + 2][m] = bv.z; Bs[lc + 3][m] = bv.w;
        }
        __syncthreads();
        #pragma unroll
        for (int kk = 0; kk < 16; ++kk) {
            float4 a0 = *(const float4*)&As[kk][ty * 8];
            float4 a1 = *(const float4*)&As[kk][ty * 8 + 4];
            float4 b0 = *(const float4*)&Bs[kk][tx * 8];
            float4 b1 = *(const float4*)&Bs[kk][tx * 8 + 4];
            float a[8] = {a0.x, a0.y, a0.z, a0.w, a1.x, a1.y, a1.z, a1.w};
            float b[8] = {b0.x, b0.y, b0.z, b0.w, b1.x, b1.y, b1.z, b1.w};
            #pragma unroll
            for (int i = 0; i < 8; ++i)
                #pragma unroll
                for (int j = 0; j < 8; ++j)
                    acc[i][j] = fmaf(a[i], b[j], acc[i][j]);
        }
        __syncthreads();
    }

    float bvals[8];
    #pragma unroll
    for (int j = 0; j < 8; ++j) bvals[j] = bias[bn + tx * 8 + j];

    #pragma unroll
    for (int i = 0; i < 8; ++i) {
        long m = bm + ty * 8 + i;
        long base = m * N + bn + tx * 8;
        float v[8];
        #pragma unroll
        for (int j = 0; j < 8; ++j) {
            float t = acc[i][j] + bvals[j];
            if (EPI == EPI_SOFTPLUS) {
                float sp = fmaxf(t, 0.f) + log1pf(expf(-fabsf(t)));
                t = fminf(fmaxf(sp, 1e-4f), 10.0f);
            } else if (EPI == EPI_RESID) {
                t += resid[base + j - (bn + tx * 8) + (bn + tx * 8)]; // = resid[base+j]
            }
            v[j] = t;
        }
        *(float4*)(C + base)     = make_float4(v[0], v[1], v[2], v[3]);
        *(float4*)(C + base + 4) = make_float4(v[4], v[5], v[6], v[7]);
    }
}

// ---------------------------------------------------------------------------
// Causal depthwise conv(4) + bias + SiLU.  x_in = g_xz[:, 0:2048]
// ---------------------------------------------------------------------------
__global__ void conv_silu_kernel(const float* __restrict__ conv_w,
                                 const float* __restrict__ conv_b) {
    int idx = blockIdx.x * blockDim.x + threadIdx.x;     // over B*L*DINNER
    if (idx >= BATCH * LSEQ * DINNER) return;
    int c = idx & (DINNER - 1);
    int t = (idx >> 11) & (LSEQ - 1);
    int b = idx >> 21;
    const float* xin = g_xz + (long)(b * LSEQ) * (2 * DINNER) + c;
    float acc = conv_b[c];
    #pragma unroll
    for (int j = 0; j < DCONV; ++j) {
        int tt = t - (DCONV - 1) + j;
        if (tt >= 0) acc = fmaf(xin[(long)tt * (2 * DINNER)], conv_w[c * DCONV + j], acc);
    }
    float sig = 1.0f / (1.0f + expf(-acc));
    g_xc[(long)(b * LSEQ + t) * DINNER + c] = acc * sig;
}

// ---------------------------------------------------------------------------
// x_proj: BC[row, 0:32] = xc[row,:] @ W[32,2048]^T + bias.  One warp / 2 rows.
// ---------------------------------------------------------------------------
__global__ void xproj_kernel(const float* __restrict__ W,
                             const float* __restrict__ bias) {
    int gw   = (blockIdx.x * blockDim.x + threadIdx.x) >> 5;   // warp id, 1024 total
    int lane = threadIdx.x & 31;
    int r0 = gw * 2;
    const float* x0 = g_xc + (long)r0 * DINNER;
    const float* x1 = x0 + DINNER;
    float acc0[32], acc1[32];
    #pragma unroll
    for (int n = 0; n < 32; ++n) { acc0[n] = 0.f; acc1[n] = 0.f; }
    for (int k0 = 0; k0 < DINNER; k0 += 32) {
        float xa = x0[k0 + lane];
        float xb = x1[k0 + lane];
        #pragma unroll
        for (int n = 0; n < 32; ++n) {
            float w = W[n * DINNER + k0 + lane];
            acc0[n] = fmaf(xa, w, acc0[n]);
            acc1[n] = fmaf(xb, w, acc1[n]);
        }
    }
    #pragma unroll
    for (int n = 0; n < 32; ++n) {
        float v0 = warp_sum32(acc0[n]);
        float v1 = warp_sum32(acc1[n]);
        if (lane == n) {
            g_bc[(long)r0 * 32 + n]       = v0 + bias[n];
            g_bc[(long)(r0 + 1) * 32 + n] = v1 + bias[n];
        }
    }
}

// ---------------------------------------------------------------------------
// Selective scan. One warp handles 2 channels; lanes 0-15 = states of channel
// 2g, lanes 16-31 = states of channel 2g+1. Bfly reductions stay inside each
// 16-lane half. Fuses the z-gate (y * silu(z)).
// ---------------------------------------------------------------------------
__global__ void scan_kernel(const float* __restrict__ A_log,
                            const float* __restrict__ Dvec) {
    int gw   = (blockIdx.x * blockDim.x + threadIdx.x) >> 5;   // 0..2047
    int lane = threadIdx.x & 31;
    int s    = lane & 15;
    int half = lane >> 4;
    int b  = gw >> 10;                 // 1024 warps per batch
    int cp = gw & 1023;
    int c  = cp * 2 + half;

    float a  = -expf(A_log[c * DSTATE + s]);
    float Dc = Dvec[c];
    float h = 0.f;

    const float* dl  = g_delta + (long)b * LSEQ * DINNER;
    const float* xcb = g_xc    + (long)b * LSEQ * DINNER;
    const float* bcb = g_bc    + (long)b * LSEQ * 2 * DSTATE;
    const float* zb  = g_xz    + (long)b * LSEQ * 2 * DINNER + DINNER;
    float*       yb  = g_y     + (long)b * LSEQ * DINNER;

    for (int t = 0; t < LSEQ; ++t) {
        float d  = dl [(long)t * DINNER + c];
        float xv = xcb[(long)t * DINNER + c];
        float Bv = bcb[t * 32 + s];
        float Cv = bcb[t * 32 + 16 + s];
        float da = expf(fminf(fmaxf(d * a, -10.0f), 0.0f));
        h = fmaf(da, h, d * Bv * xv);
        if ((t & 15) == 15) {
            float ss = h * h;
            ss += __shfl_xor_sync(0xffffffffu, ss, 8);
            ss += __shfl_xor_sync(0xffffffffu, ss, 4);
            ss += __shfl_xor_sync(0xffffffffu, ss, 2);
            ss += __shfl_xor_sync(0xffffffffu, ss, 1);
            float hn = fmaxf(sqrtf(ss), 1e-6f);
            if (hn > 10.0f) h *= 10.0f / hn;
        }
        float p = Cv * h;
        p += __shfl_xor_sync(0xffffffffu, p, 8);
        p += __shfl_xor_sync(0xffffffffu, p, 4);
        p += __shfl_xor_sync(0xffffffffu, p, 2);
        p += __shfl_xor_sync(0xffffffffu, p, 1);
        if (s == 0) {
            float yv = p + Dc * xv;
            float z  = zb[(long)t * (2 * DINNER) + c];
            yv *= z / (1.0f + expf(-z));
            yb[(long)t * DINNER + c] = yv;
        }
    }
}

// ---------------------------------------------------------------------------
// Launch
// ---------------------------------------------------------------------------
extern "C" void kernel_launch(void* const* d_in, const int* in_sizes, int n_in,
                              void* d_out, int out_size) {
    const float* x             = (const float*)d_in[0];
    const float* in_proj_w     = (const float*)d_in[1];
    const float* in_proj_b     = (const float*)d_in[2];
    const float* conv_w        = (const float*)d_in[3];
    const float* conv_b        = (const float*)d_in[4];
    const float* x_proj_w      = (const float*)d_in[5];
    const float* x_proj_b      = (const float*)d_in[6];
    const float* dt_proj_w     = (const float*)d_in[7];
    const float* dt_proj_b     = (const float*)d_in[8];
    const float* A_log         = (const float*)d_in[9];
    const float* Dvec          = (const float*)d_in[10];
    const float* out_proj_w    = (const float*)d_in[11];
    const float* out_proj_b    = (const float*)d_in[12];
    const float* in_norm_alpha = (const float*)d_in[13];
    const float* in_norm_bias  = (const float*)d_in[14];
    const float* norm_alpha    = (const float*)d_in[15];
    const float* norm_bias     = (const float*)d_in[16];
    float* out = (float*)d_out;

    float* xn    = nullptr; cudaGetSymbolAddress((void**)&xn,    g_xn);
    float* xz    = nullptr; cudaGetSymbolAddress((void**)&xz,    g_xz);
    float* xc    = nullptr; cudaGetSymbolAddress((void**)&xc,    g_xc);
    float* delta = nullptr; cudaGetSymbolAddress((void**)&delta, g_delta);
    float* ybuf  = nullptr; cudaGetSymbolAddress((void**)&ybuf,  g_y);
    float* obuf  = nullptr; cudaGetSymbolAddress((void**)&obuf,  g_out);

    // 1. input layernorm
    ln_kernel<<<ROWS, 256>>>(x, in_norm_alpha, in_norm_bias, xn);

    // 2. in_proj: xz = xn @ W^T + b   (2048 x 4096 x 1024)
    gemm_nt<EPI_BIAS><<<dim3(4096 / 128, ROWS / 128), 256>>>(
        xn, in_proj_w, in_proj_b, nullptr, xz, ROWS, 2 * DINNER, DMODEL);

    // 3. causal depthwise conv + silu
    conv_silu_kernel<<<(BATCH * LSEQ * DINNER) / 256, 256>>>(conv_w, conv_b);

    // 4. x_proj -> B,C   (warp per 2 rows; 1024 warps)
    xproj_kernel<<<128, 256>>>(x_proj_w, x_proj_b);

    // 5. dt_proj + softplus + clip   (2048 x 2048 x 2048)
    gemm_nt<EPI_SOFTPLUS><<<dim3(DINNER / 128, ROWS / 128), 256>>>(
        xc, dt_proj_w, dt_proj_b, nullptr, delta, ROWS, DINNER, DINNER);

    // 6. selective scan + z gate
    scan_kernel<<<256, 256>>>(A_log, Dvec);

    // 7. out_proj + residual   (2048 x 1024 x 2048)
    gemm_nt<EPI_RESID><<<dim3(DMODEL / 128, ROWS / 128), 256>>>(
        ybuf, out_proj_w, out_proj_b, x, obuf, ROWS, DMODEL, DINNER);

    // 8. final layernorm -> d_out
    ln_kernel<<<ROWS, 256>>>(obuf, norm_alpha, norm_bias, out);
}

// round 4
// speedup vs baseline: 1.4439x; 1.4439x over previous
#include <cuda_runtime.h>
#include <cuda_bf16.h>
#include <math.h>
#include <stdint.h>

// ---------------------------------------------------------------------------
// Shapes (fixed): B=2, L=1024, d_model=1024, d_state=16, d_conv=4, d_inner=2048
// ---------------------------------------------------------------------------
#define BATCH    2
#define LSEQ     1024
#define DMODEL   1024
#define DSTATE   16
#define DCONV    4
#define DINNER   2048
#define ROWS     (BATCH * LSEQ)

// ---------------------------------------------------------------------------
// Scratch (device globals; no allocation allowed)
// ---------------------------------------------------------------------------
__device__ __nv_bfloat16 g_xn_h[ROWS * DMODEL], g_xn_l[ROWS * DMODEL];
__device__ __nv_bfloat16 g_wi_h[2 * DINNER * DMODEL], g_wi_l[2 * DINNER * DMODEL];
__device__ __nv_bfloat16 g_wd_h[DINNER * DINNER], g_wd_l[DINNER * DINNER];
__device__ __nv_bfloat16 g_wo_h[DMODEL * DINNER], g_wo_l[DMODEL * DINNER];
__device__ __nv_bfloat16 g_xc_h[ROWS * DINNER], g_xc_l[ROWS * DINNER];
__device__ __nv_bfloat16 g_y_h [ROWS * DINNER], g_y_l [ROWS * DINNER];
__device__ float g_xz   [ROWS * 2 * DINNER];
__device__ float g_xc   [ROWS * DINNER];
__device__ float g_bc   [ROWS * 2 * DSTATE];
__device__ float g_delta[ROWS * DINNER];
__device__ float g_out  [ROWS * DMODEL];

// ---------------------------------------------------------------------------
// PTX helpers (all plain sm_80+ features; no 'a'-suffix instructions)
// ---------------------------------------------------------------------------
__device__ __forceinline__ uint32_t smem_to_u32(const void* p) {
    uint32_t a;
    asm("{ .reg .u64 t; cvta.to.shared.u64 t, %1; cvt.u32.u64 %0, t; }" : "=r"(a) : "l"(p));
    return a;
}
#define CP_ASYNC16(dst, src) \
    asm volatile("cp.async.cg.shared.global [%0], [%1], 16;" :: "r"(dst), "l"(src))
#define CP_COMMIT() asm volatile("cp.async.commit_group;" ::: "memory")
#define CP_WAIT(n)  asm volatile("cp.async.wait_group %0;" :: "n"(n) : "memory")

__device__ __forceinline__ void ldsm_x4(uint32_t* r, uint32_t addr) {
    asm volatile("ldmatrix.sync.aligned.m8n8.x4.shared.b16 {%0,%1,%2,%3}, [%4];"
        : "=r"(r[0]), "=r"(r[1]), "=r"(r[2]), "=r"(r[3]) : "r"(addr));
}
__device__ __forceinline__ void mma_bf16(float* c, const uint32_t* a, const uint32_t* b) {
    asm volatile(
        "mma.sync.aligned.m16n8k16.row.col.f32.bf16.bf16.f32 "
        "{%0,%1,%2,%3}, {%4,%5,%6,%7}, {%8,%9}, {%0,%1,%2,%3};"
        : "+f"(c[0]), "+f"(c[1]), "+f"(c[2]), "+f"(c[3])
        : "r"(a[0]), "r"(a[1]), "r"(a[2]), "r"(a[3]), "r"(b[0]), "r"(b[1]));
}

// ---------------------------------------------------------------------------
// LayerNorm (ddof=1 std, eps on std). SPLIT=1 emits bf16 hi/lo, else fp32.
// ---------------------------------------------------------------------------
__device__ __forceinline__ float warp_sum32(float v) {
    #pragma unroll
    for (int m = 16; m > 0; m >>= 1) v += __shfl_xor_sync(0xffffffffu, v, m);
    return v;
}

template<int SPLIT>
__global__ void ln_kernel(const float* __restrict__ X,
                          const float* __restrict__ alpha,
                          const float* __restrict__ beta,
                          float* __restrict__ Y,
                          __nv_bfloat16* __restrict__ Yh,
                          __nv_bfloat16* __restrict__ Yl) {
    __shared__ float sh[2][8];
    int row = blockIdx.x;
    int tid = threadIdx.x;
    const float* xr = X + (long)row * DMODEL;
    float4 xv = *(const float4*)(xr + tid * 4);
    float s  = xv.x + xv.y + xv.z + xv.w;
    float ss = xv.x*xv.x + xv.y*xv.y + xv.z*xv.z + xv.w*xv.w;
    s = warp_sum32(s); ss = warp_sum32(ss);
    if ((tid & 31) == 0) { sh[0][tid >> 5] = s; sh[1][tid >> 5] = ss; }
    __syncthreads();
    float S = 0.f, SS = 0.f;
    #pragma unroll
    for (int w = 0; w < 8; ++w) { S += sh[0][w]; SS += sh[1][w]; }
    float mean = S * (1.0f / (float)DMODEL);
    float var  = fmaxf((SS - (float)DMODEL * mean * mean) * (1.0f / (float)(DMODEL - 1)), 0.f);
    float inv  = 1.0f / (sqrtf(var) + 1e-6f);
    float4 av = *(const float4*)(alpha + tid * 4);
    float4 bv = *(const float4*)(beta  + tid * 4);
    float o[4];
    o[0] = av.x * (xv.x - mean) * inv + bv.x;
    o[1] = av.y * (xv.y - mean) * inv + bv.y;
    o[2] = av.z * (xv.z - mean) * inv + bv.z;
    o[3] = av.w * (xv.w - mean) * inv + bv.w;
    long base = (long)row * DMODEL + tid * 4;
    if (SPLIT) {
        __nv_bfloat16 h[4], l[4];
        #pragma unroll
        for (int j = 0; j < 4; ++j) {
            h[j] = __float2bfloat16(o[j]);
            l[j] = __float2bfloat16(o[j] - __bfloat162float(h[j]));
        }
        *(uint2*)(Yh + base) = *(uint2*)h;
        *(uint2*)(Yl + base) = *(uint2*)l;
    } else {
        *(float4*)(Y + base) = make_float4(o[0], o[1], o[2], o[3]);
    }
}

// ---------------------------------------------------------------------------
// fp32 -> bf16 hi/lo split (weights)
// ---------------------------------------------------------------------------
__global__ void split_kernel(const float* __restrict__ X,
                             __nv_bfloat16* __restrict__ H,
                             __nv_bfloat16* __restrict__ L, int n4) {
    int i = blockIdx.x * blockDim.x + threadIdx.x;
    if (i >= n4) return;
    float4 v = *(const float4*)(X + (long)i * 4);
    float o[4] = {v.x, v.y, v.z, v.w};
    __nv_bfloat16 h[4], l[4];
    #pragma unroll
    for (int j = 0; j < 4; ++j) {
        h[j] = __float2bfloat16(o[j]);
        l[j] = __float2bfloat16(o[j] - __bfloat162float(h[j]));
    }
    *(uint2*)(H + (long)i * 4) = *(uint2*)h;
    *(uint2*)(L + (long)i * 4) = *(uint2*)l;
}

// ---------------------------------------------------------------------------
// HMMA split-bf16 GEMM: C[M,N] = (Ah+Al)[M,K] @ (Bh+Bl)[N,K]^T
//   = Ah·Bh + Ah·Bl + Al·Bh   (lo·lo dropped)
// Block tile 128x128, BK=32, 8 warps (2m x 4n), warp tile 64x32.
// cp.async double-buffered. SMEM rows padded to 80B (conflict-free ldmatrix).
// EPI: 0 bias, 1 bias+softplus+clip, 2 bias+residual
// ---------------------------------------------------------------------------
#define EPI_BIAS     0
#define EPI_SOFTPLUS 1
#define EPI_RESID    2
#define ROWB      80                       // padded row bytes (32 bf16 -> 80B)
#define ARR_SZ    (128 * ROWB)             // 10240 B per operand array
#define STAGE_SZ  (4 * ARR_SZ)             // 40960 B per stage
#define GEMM_SMEM (2 * STAGE_SZ)           // 81920 B

template<int EPI>
__global__ __launch_bounds__(256, 1)
void gemm_hmma(const __nv_bfloat16* __restrict__ Ah, const __nv_bfloat16* __restrict__ Al,
               const __nv_bfloat16* __restrict__ Bh, const __nv_bfloat16* __restrict__ Bl,
               const float* __restrict__ bias, const float* __restrict__ resid,
               float* __restrict__ C, int M, int N, int K) {
    extern __shared__ char smem[];
    uint32_t sb = smem_to_u32(smem);
    int tid  = threadIdx.x;
    int lane = tid & 31;
    int wid  = tid >> 5;
    int wm   = wid & 1;                    // 2 m-groups of 64
    int wn   = wid >> 1;                   // 4 n-groups of 32
    int bm = blockIdx.y * 128, bn = blockIdx.x * 128;

    const __nv_bfloat16* srcs[4] = {
        Ah + (long)bm * K, Bh + (long)bn * K, Al + (long)bm * K, Bl + (long)bn * K };

    // per-thread load slots (8 x 16B chunks per stage)
    int s_arr[8], s_row[8], s_c[8];
    #pragma unroll
    for (int i = 0; i < 8; ++i) {
        int id = tid + i * 256;            // 0..2047
        s_arr[i] = id >> 9;
        int rem = id & 511;
        s_row[i] = rem >> 2;
        s_c[i]   = rem & 3;
    }

    auto load_stage = [&](int kt, int buf) {
        #pragma unroll
        for (int i = 0; i < 8; ++i) {
            uint32_t dst = sb + buf * STAGE_SZ + s_arr[i] * ARR_SZ
                         + s_row[i] * ROWB + s_c[i] * 16;
            const __nv_bfloat16* src = srcs[s_arr[i]] + (long)s_row[i] * K
                                     + kt * 32 + s_c[i] * 8;
            CP_ASYNC16(dst, src);
        }
        CP_COMMIT();
    };

    float c[4][4][4];
    #pragma unroll
    for (int mt = 0; mt < 4; ++mt)
        #pragma unroll
        for (int nj = 0; nj < 4; ++nj)
            #pragma unroll
            for (int r = 0; r < 4; ++r) c[mt][nj][r] = 0.f;

    // ldmatrix address components (constant per thread)
    int a_row = wm * 64 + (lane & 15);                       // + mt*16
    int a_kb  = (lane >> 4) << 4;                            // + ks*32 (bytes)
    int b_row = wn * 32 + ((lane >> 4) << 3) + (lane & 7);   // + nt*16
    int b_kb  = ((lane >> 3) & 1) << 4;                      // + ks*32 (bytes)

    const int KT = K >> 5;
    load_stage(0, 0);
    for (int kt = 0; kt < KT; ++kt) {
        int buf = kt & 1;
        if (kt + 1 < KT) { load_stage(kt + 1, buf ^ 1); CP_WAIT(1); }
        else             { CP_WAIT(0); }
        __syncthreads();

        uint32_t base = sb + buf * STAGE_SZ;
        #pragma unroll
        for (int ks = 0; ks < 2; ++ks) {                     // two k16 sub-slices
            uint32_t kboff = ks * 32;
            uint32_t ah[4][4], al[4][4], bh[4][2], bl[4][2];
            #pragma unroll
            for (int mt = 0; mt < 4; ++mt) {
                uint32_t off = (uint32_t)((a_row + mt * 16) * ROWB) + a_kb + kboff;
                ldsm_x4(ah[mt], base + 0 * ARR_SZ + off);
                ldsm_x4(al[mt], base + 2 * ARR_SZ + off);
            }
            #pragma unroll
            for (int nt = 0; nt < 2; ++nt) {
                // non-trans: [N,K] row-major already matches mma's col-B fragment
                uint32_t off = (uint32_t)((b_row + nt * 16) * ROWB) + b_kb + kboff;
                uint32_t t0[4], t1[4];
                ldsm_x4(t0, base + 1 * ARR_SZ + off);
                ldsm_x4(t1, base + 3 * ARR_SZ + off);
                bh[nt*2][0] = t0[0]; bh[nt*2][1] = t0[1];
                bh[nt*2+1][0] = t0[2]; bh[nt*2+1][1] = t0[3];
                bl[nt*2][0] = t1[0]; bl[nt*2][1] = t1[1];
                bl[nt*2+1][0] = t1[2]; bl[nt*2+1][1] = t1[3];
            }
            #pragma unroll
            for (int mt = 0; mt < 4; ++mt)
                #pragma unroll
                for (int nj = 0; nj < 4; ++nj) {
                    mma_bf16(c[mt][nj], ah[mt], bh[nj]);
                    mma_bf16(c[mt][nj], ah[mt], bl[nj]);
                    mma_bf16(c[mt][nj], al[mt], bh[nj]);
                }
        }
        __syncthreads();
    }

    // epilogue
    #pragma unroll
    for (int mt = 0; mt < 4; ++mt) {
        #pragma unroll
        for (int nj = 0; nj < 4; ++nj) {
            int row0 = bm + wm * 64 + mt * 16 + (lane >> 2);
            int col  = bn + wn * 32 + nj * 8 + (lane & 3) * 2;
            float b0 = bias[col], b1 = bias[col + 1];
            float v[4] = { c[mt][nj][0] + b0, c[mt][nj][1] + b1,
                           c[mt][nj][2] + b0, c[mt][nj][3] + b1 };
            if (EPI == EPI_SOFTPLUS) {
                #pragma unroll
                for (int r = 0; r < 4; ++r) {
                    float sp = fmaxf(v[r], 0.f) + log1pf(expf(-fabsf(v[r])));
                    v[r] = fminf(fmaxf(sp, 1e-4f), 10.0f);
                }
            } else if (EPI == EPI_RESID) {
                long p0 = (long)row0 * N + col, p1 = (long)(row0 + 8) * N + col;
                v[0] += resid[p0]; v[1] += resid[p0 + 1];
                v[2] += resid[p1]; v[3] += resid[p1 + 1];
            }
            *(float2*)(C + (long)row0 * N + col)       = make_float2(v[0], v[1]);
            *(float2*)(C + (long)(row0 + 8) * N + col) = make_float2(v[2], v[3]);
        }
    }
}

// ---------------------------------------------------------------------------
// Causal depthwise conv(4) + bias + SiLU; emits fp32 + bf16 hi/lo
// ---------------------------------------------------------------------------
__global__ void conv_silu_kernel(const float* __restrict__ conv_w,
                                 const float* __restrict__ conv_b) {
    int idx = blockIdx.x * blockDim.x + threadIdx.x;
    if (idx >= BATCH * LSEQ * DINNER) return;
    int c = idx & (DINNER - 1);
    int t = (idx >> 11) & (LSEQ - 1);
    int b = idx >> 21;
    const float* xin = g_xz + (long)(b * LSEQ) * (2 * DINNER) + c;
    float acc = conv_b[c];
    #pragma unroll
    for (int j = 0; j < DCONV; ++j) {
        int tt = t - (DCONV - 1) + j;
        if (tt >= 0) acc = fmaf(xin[(long)tt * (2 * DINNER)], conv_w[c * DCONV + j], acc);
    }
    float sig = 1.0f / (1.0f + expf(-acc));
    float yv = acc * sig;
    long o = (long)(b * LSEQ + t) * DINNER + c;
    g_xc[o] = yv;
    __nv_bfloat16 h = __float2bfloat16(yv);
    g_xc_h[o] = h;
    g_xc_l[o] = __float2bfloat16(yv - __bfloat162float(h));
}

// ---------------------------------------------------------------------------
// x_proj: BC = xc @ W[32,2048]^T + b. Block = 32 rows x 32 outs, K-tiled smem.
// ---------------------------------------------------------------------------
__global__ __launch_bounds__(256)
void xproj_kernel(const float* __restrict__ W, const float* __restrict__ bias) {
    __shared__ float Xs[32][65];
    __shared__ float Ws[32][65];
    int tid = threadIdx.x;
    int row0 = blockIdx.x * 32;
    int rg = (tid >> 5) * 4;
    int n  = tid & 31;
    float acc[4] = {0.f, 0.f, 0.f, 0.f};
    for (int k0 = 0; k0 < DINNER; k0 += 64) {
        #pragma unroll
        for (int i = 0; i < 2; ++i) {
            int id = tid * 2 + i;
            int r = id >> 4, c4 = (id & 15) * 4;
            float4 xv = *(const float4*)(g_xc + (long)(row0 + r) * DINNER + k0 + c4);
            Xs[r][c4] = xv.x; Xs[r][c4+1] = xv.y; Xs[r][c4+2] = xv.z; Xs[r][c4+3] = xv.w;
            float4 wv = *(const float4*)(W + (long)r * DINNER + k0 + c4);
            Ws[r][c4] = wv.x; Ws[r][c4+1] = wv.y; Ws[r][c4+2] = wv.z; Ws[r][c4+3] = wv.w;
        }
        __syncthreads();
        #pragma unroll
        for (int kk = 0; kk < 64; ++kk) {
            float w = Ws[n][kk];
            #pragma unroll
            for (int i = 0; i < 4; ++i) acc[i] = fmaf(Xs[rg + i][kk], w, acc[i]);
        }
        __syncthreads();
    }
    float bv = bias[n];
    #pragma unroll
    for (int i = 0; i < 4; ++i)
        g_bc[(long)(row0 + rg + i) * 32 + n] = acc[i] + bv;
}

// ---------------------------------------------------------------------------
// Selective scan + z-gate; emits bf16 hi/lo of gated y.
// Warp = 2 channels (16 lanes = 16 states each).
// ---------------------------------------------------------------------------
__global__ void scan_kernel(const float* __restrict__ A_log,
                            const float* __restrict__ Dvec) {
    int gw   = (blockIdx.x * blockDim.x + threadIdx.x) >> 5;
    int lane = threadIdx.x & 31;
    int s    = lane & 15;
    int half = lane >> 4;
    int b  = gw >> 10;
    int cp = gw & 1023;
    int c  = cp * 2 + half;

    float a  = -expf(A_log[c * DSTATE + s]);
    float Dc = Dvec[c];
    float h = 0.f;

    const float* dl  = g_delta + (long)b * LSEQ * DINNER;
    const float* xcb = g_xc    + (long)b * LSEQ * DINNER;
    const float* bcb = g_bc    + (long)b * LSEQ * 2 * DSTATE;
    const float* zb  = g_xz    + (long)b * LSEQ * 2 * DINNER + DINNER;

    for (int t = 0; t < LSEQ; ++t) {
        float d  = dl [(long)t * DINNER + c];
        float xv = xcb[(long)t * DINNER + c];
        float Bv = bcb[t * 32 + s];
        float Cv = bcb[t * 32 + 16 + s];
        float da = expf(fminf(fmaxf(d * a, -10.0f), 0.0f));
        h = fmaf(da, h, d * Bv * xv);
        if ((t & 15) == 15) {
            float ss = h * h;
            ss += __shfl_xor_sync(0xffffffffu, ss, 8);
            ss += __shfl_xor_sync(0xffffffffu, ss, 4);
            ss += __shfl_xor_sync(0xffffffffu, ss, 2);
            ss += __shfl_xor_sync(0xffffffffu, ss, 1);
            float hn = fmaxf(sqrtf(ss), 1e-6f);
            if (hn > 10.0f) h *= 10.0f / hn;
        }
        float p = Cv * h;
        p += __shfl_xor_sync(0xffffffffu, p, 8);
        p += __shfl_xor_sync(0xffffffffu, p, 4);
        p += __shfl_xor_sync(0xffffffffu, p, 2);
        p += __shfl_xor_sync(0xffffffffu, p, 1);
        if (s == 0) {
            float yv = p + Dc * xv;
            float z  = zb[(long)t * (2 * DINNER) + c];
            yv *= z / (1.0f + expf(-z));
            long o = (long)b * LSEQ * DINNER + (long)t * DINNER + c;
            __nv_bfloat16 hh = __float2bfloat16(yv);
            g_y_h[o] = hh;
            g_y_l[o] = __float2bfloat16(yv - __bfloat162float(hh));
        }
    }
}

// ---------------------------------------------------------------------------
// Launch
// ---------------------------------------------------------------------------
extern "C" void kernel_launch(void* const* d_in, const int* in_sizes, int n_in,
                              void* d_out, int out_size) {
    const float* x             = (const float*)d_in[0];
    const float* in_proj_w     = (const float*)d_in[1];
    const float* in_proj_b     = (const float*)d_in[2];
    const float* conv_w        = (const float*)d_in[3];
    const float* conv_b        = (const float*)d_in[4];
    const float* x_proj_w      = (const float*)d_in[5];
    const float* x_proj_b      = (const float*)d_in[6];
    const float* dt_proj_w     = (const float*)d_in[7];
    const float* dt_proj_b     = (const float*)d_in[8];
    const float* A_log         = (const float*)d_in[9];
    const float* Dvec          = (const float*)d_in[10];
    const float* out_proj_w    = (const float*)d_in[11];
    const float* out_proj_b    = (const float*)d_in[12];
    const float* in_norm_alpha = (const float*)d_in[13];
    const float* in_norm_bias  = (const float*)d_in[14];
    const float* norm_alpha    = (const float*)d_in[15];
    const float* norm_bias     = (const float*)d_in[16];
    float* out = (float*)d_out;

    __nv_bfloat16 *xn_h, *xn_l, *wi_h, *wi_l, *wd_h, *wd_l, *wo_h, *wo_l;
    __nv_bfloat16 *xc_h, *xc_l, *y_h, *y_l;
    float *xz, *delta, *obuf;
    cudaGetSymbolAddress((void**)&xn_h, g_xn_h); cudaGetSymbolAddress((void**)&xn_l, g_xn_l);
    cudaGetSymbolAddress((void**)&wi_h, g_wi_h); cudaGetSymbolAddress((void**)&wi_l, g_wi_l);
    cudaGetSymbolAddress((void**)&wd_h, g_wd_h); cudaGetSymbolAddress((void**)&wd_l, g_wd_l);
    cudaGetSymbolAddress((void**)&wo_h, g_wo_h); cudaGetSymbolAddress((void**)&wo_l, g_wo_l);
    cudaGetSymbolAddress((void**)&xc_h, g_xc_h); cudaGetSymbolAddress((void**)&xc_l, g_xc_l);
    cudaGetSymbolAddress((void**)&y_h,  g_y_h);  cudaGetSymbolAddress((void**)&y_l,  g_y_l);
    cudaGetSymbolAddress((void**)&xz,    g_xz);
    cudaGetSymbolAddress((void**)&delta, g_delta);
    cudaGetSymbolAddress((void**)&obuf,  g_out);

    cudaFuncSetAttribute(gemm_hmma<EPI_BIAS>,     cudaFuncAttributeMaxDynamicSharedMemorySize, GEMM_SMEM);
    cudaFuncSetAttribute(gemm_hmma<EPI_SOFTPLUS>, cudaFuncAttributeMaxDynamicSharedMemorySize, GEMM_SMEM);
    cudaFuncSetAttribute(gemm_hmma<EPI_RESID>,    cudaFuncAttributeMaxDynamicSharedMemorySize, GEMM_SMEM);

    // weight splits (independent of activations)
    split_kernel<<<(2 * DINNER * DMODEL / 4 + 255) / 256, 256>>>(in_proj_w,  wi_h, wi_l, 2 * DINNER * DMODEL / 4);
    split_kernel<<<(DINNER * DINNER / 4 + 255) / 256, 256>>>(dt_proj_w,  wd_h, wd_l, DINNER * DINNER / 4);
    split_kernel<<<(DMODEL * DINNER / 4 + 255) / 256, 256>>>(out_proj_w, wo_h, wo_l, DMODEL * DINNER / 4);

    // 1. input layernorm -> bf16 split
    ln_kernel<1><<<ROWS, 256>>>(x, in_norm_alpha, in_norm_bias, nullptr, xn_h, xn_l);

    // 2. in_proj (2048 x 4096 x 1024)
    gemm_hmma<EPI_BIAS><<<dim3(32, 16), 256, GEMM_SMEM>>>(
        xn_h, xn_l, wi_h, wi_l, in_proj_b, nullptr, xz, ROWS, 2 * DINNER, DMODEL);

    // 3. conv + silu
    conv_silu_kernel<<<(BATCH * LSEQ * DINNER) / 256, 256>>>(conv_w, conv_b);

    // 4. x_proj -> B,C
    xproj_kernel<<<ROWS / 32, 256>>>(x_proj_w, x_proj_b);

    // 5. dt_proj + softplus + clip (2048 x 2048 x 2048)
    gemm_hmma<EPI_SOFTPLUS><<<dim3(16, 16), 256, GEMM_SMEM>>>(
        xc_h, xc_l, wd_h, wd_l, dt_proj_b, nullptr, delta, ROWS, DINNER, DINNER);

    // 6. selective scan + z gate
    scan_kernel<<<256, 256>>>(A_log, Dvec);

    // 7. out_proj + residual (2048 x 1024 x 2048)
    gemm_hmma<EPI_RESID><<<dim3(8, 16), 256, GEMM_SMEM>>>(
        y_h, y_l, wo_h, wo_l, out_proj_b, x, obuf, ROWS, DMODEL, DINNER);

    // 8. final layernorm -> d_out
    ln_kernel<0><<<ROWS, 256>>>(obuf, norm_alpha, norm_bias, out, nullptr, nullptr);
}

// round 5
// speedup vs baseline: 1.8896x; 1.3087x over previous
#include <cuda_runtime.h>
#include <cuda_bf16.h>
#include <math.h>
#include <stdint.h>

// ---------------------------------------------------------------------------
// Shapes (fixed): B=2, L=1024, d_model=1024, d_state=16, d_conv=4, d_inner=2048
// ---------------------------------------------------------------------------
#define BATCH    2
#define LSEQ     1024
#define DMODEL   1024
#define DSTATE   16
#define DCONV    4
#define DINNER   2048
#define ROWS     (BATCH * LSEQ)

// ---------------------------------------------------------------------------
// Scratch (device globals; no allocation allowed)
// ---------------------------------------------------------------------------
__device__ __nv_bfloat16 g_xn_h[ROWS * DMODEL];
__device__ __nv_bfloat16 g_wi_h[2 * DINNER * DMODEL];
__device__ __nv_bfloat16 g_wd_h[DINNER * DINNER];
__device__ __nv_bfloat16 g_wo_h[DMODEL * DINNER];
__device__ __nv_bfloat16 g_xc_h[ROWS * DINNER];
__device__ __nv_bfloat16 g_y_h [ROWS * DINNER];
__device__ float g_xz   [ROWS * 2 * DINNER];
__device__ float g_xc   [ROWS * DINNER];
__device__ float g_bc   [ROWS * 2 * DSTATE];
__device__ float g_delta[ROWS * DINNER];
__device__ float g_out  [ROWS * DMODEL];

// ---------------------------------------------------------------------------
// PTX helpers (plain sm_80+ features only)
// ---------------------------------------------------------------------------
__device__ __forceinline__ uint32_t smem_to_u32(const void* p) {
    uint32_t a;
    asm("{ .reg .u64 t; cvta.to.shared.u64 t, %1; cvt.u32.u64 %0, t; }" : "=r"(a) : "l"(p));
    return a;
}
#define CP_ASYNC16(dst, src) \
    asm volatile("cp.async.cg.shared.global [%0], [%1], 16;" :: "r"(dst), "l"(src))
#define CP_COMMIT() asm volatile("cp.async.commit_group;" ::: "memory")
#define CP_WAIT(n)  asm volatile("cp.async.wait_group %0;" :: "n"(n) : "memory")

__device__ __forceinline__ void ldsm_x4(uint32_t* r, uint32_t addr) {
    asm volatile("ldmatrix.sync.aligned.m8n8.x4.shared.b16 {%0,%1,%2,%3}, [%4];"
        : "=r"(r[0]), "=r"(r[1]), "=r"(r[2]), "=r"(r[3]) : "r"(addr));
}
__device__ __forceinline__ void mma_bf16(float* c, const uint32_t* a, const uint32_t* b) {
    asm volatile(
        "mma.sync.aligned.m16n8k16.row.col.f32.bf16.bf16.f32 "
        "{%0,%1,%2,%3}, {%4,%5,%6,%7}, {%8,%9}, {%0,%1,%2,%3};"
        : "+f"(c[0]), "+f"(c[1]), "+f"(c[2]), "+f"(c[3])
        : "r"(a[0]), "r"(a[1]), "r"(a[2]), "r"(a[3]), "r"(b[0]), "r"(b[1]));
}

// ---------------------------------------------------------------------------
// LayerNorm (ddof=1 std, eps on std). SPLIT=1 emits bf16, else fp32.
// ---------------------------------------------------------------------------
__device__ __forceinline__ float warp_sum32(float v) {
    #pragma unroll
    for (int m = 16; m > 0; m >>= 1) v += __shfl_xor_sync(0xffffffffu, v, m);
    return v;
}

template<int SPLIT>
__global__ void ln_kernel(const float* __restrict__ X,
                          const float* __restrict__ alpha,
                          const float* __restrict__ beta,
                          float* __restrict__ Y,
                          __nv_bfloat16* __restrict__ Yh) {
    __shared__ float sh[2][8];
    int row = blockIdx.x;
    int tid = threadIdx.x;
    const float* xr = X + (long)row * DMODEL;
    float4 xv = *(const float4*)(xr + tid * 4);
    float s  = xv.x + xv.y + xv.z + xv.w;
    float ss = xv.x*xv.x + xv.y*xv.y + xv.z*xv.z + xv.w*xv.w;
    s = warp_sum32(s); ss = warp_sum32(ss);
    if ((tid & 31) == 0) { sh[0][tid >> 5] = s; sh[1][tid >> 5] = ss; }
    __syncthreads();
    float S = 0.f, SS = 0.f;
    #pragma unroll
    for (int w = 0; w < 8; ++w) { S += sh[0][w]; SS += sh[1][w]; }
    float mean = S * (1.0f / (float)DMODEL);
    float var  = fmaxf((SS - (float)DMODEL * mean * mean) * (1.0f / (float)(DMODEL - 1)), 0.f);
    float inv  = 1.0f / (sqrtf(var) + 1e-6f);
    float4 av = *(const float4*)(alpha + tid * 4);
    float4 bv = *(const float4*)(beta  + tid * 4);
    float o[4];
    o[0] = av.x * (xv.x - mean) * inv + bv.x;
    o[1] = av.y * (xv.y - mean) * inv + bv.y;
    o[2] = av.z * (xv.z - mean) * inv + bv.z;
    o[3] = av.w * (xv.w - mean) * inv + bv.w;
    long base = (long)row * DMODEL + tid * 4;
    if (SPLIT) {
        __nv_bfloat16 h[4];
        #pragma unroll
        for (int j = 0; j < 4; ++j) h[j] = __float2bfloat16(o[j]);
        *(uint2*)(Yh + base) = *(uint2*)h;
    } else {
        *(float4*)(Y + base) = make_float4(o[0], o[1], o[2], o[3]);
    }
}

// ---------------------------------------------------------------------------
// fp32 -> bf16 convert (weights)
// ---------------------------------------------------------------------------
__global__ void cvt_kernel(const float* __restrict__ X,
                           __nv_bfloat16* __restrict__ H, int n4) {
    int i = blockIdx.x * blockDim.x + threadIdx.x;
    if (i >= n4) return;
    float4 v = *(const float4*)(X + (long)i * 4);
    __nv_bfloat16 h[4] = { __float2bfloat16(v.x), __float2bfloat16(v.y),
                           __float2bfloat16(v.z), __float2bfloat16(v.w) };
    *(uint2*)(H + (long)i * 4) = *(uint2*)h;
}

// ---------------------------------------------------------------------------
// Single-pass bf16 HMMA GEMM: C[M,N] = A[M,K] @ B[N,K]^T (+ epilogue)
// Block tile 128x128, BK=32, 8 warps (2m x 4n), warp tile 64x32.
// 3-stage cp.async pipeline, 2 CTAs/SM. SMEM rows padded to 80B.
// EPI: 0 bias, 1 bias+softplus+clip, 2 bias+residual
// ---------------------------------------------------------------------------
#define EPI_BIAS     0
#define EPI_SOFTPLUS 1
#define EPI_RESID    2
#define ROWB      80                       // padded row bytes (32 bf16 -> 80B)
#define ARR_SZ    (128 * ROWB)             // 10240 B per operand
#define STAGE_SZ  (2 * ARR_SZ)             // 20480 B per stage
#define NSTAGE    3
#define GEMM_SMEM (NSTAGE * STAGE_SZ)      // 61440 B

template<int EPI>
__global__ __launch_bounds__(256, 2)
void gemm_hmma(const __nv_bfloat16* __restrict__ A, const __nv_bfloat16* __restrict__ B,
               const float* __restrict__ bias, const float* __restrict__ resid,
               float* __restrict__ C, int M, int N, int K) {
    extern __shared__ char smem[];
    uint32_t sb = smem_to_u32(smem);
    int tid  = threadIdx.x;
    int lane = tid & 31;
    int wid  = tid >> 5;
    int wm   = wid & 1;                    // 2 m-groups of 64
    int wn   = wid >> 1;                   // 4 n-groups of 32
    int bm = blockIdx.y * 128, bn = blockIdx.x * 128;

    const __nv_bfloat16* srcs[2] = { A + (long)bm * K, B + (long)bn * K };

    // per-thread load slots (4 x 16B chunks per stage)
    int s_arr[4], s_row[4], s_c[4];
    #pragma unroll
    for (int i = 0; i < 4; ++i) {
        int id = tid + i * 256;            // 0..1023
        s_arr[i] = id >> 9;
        int rem = id & 511;
        s_row[i] = rem >> 2;
        s_c[i]   = rem & 3;
    }

    auto load_stage = [&](int kt, int buf) {
        #pragma unroll
        for (int i = 0; i < 4; ++i) {
            uint32_t dst = sb + buf * STAGE_SZ + s_arr[i] * ARR_SZ
                         + s_row[i] * ROWB + s_c[i] * 16;
            const __nv_bfloat16* src = srcs[s_arr[i]] + (long)s_row[i] * K
                                     + kt * 32 + s_c[i] * 8;
            CP_ASYNC16(dst, src);
        }
        CP_COMMIT();
    };

    float c[4][4][4];
    #pragma unroll
    for (int mt = 0; mt < 4; ++mt)
        #pragma unroll
        for (int nj = 0; nj < 4; ++nj)
            #pragma unroll
            for (int r = 0; r < 4; ++r) c[mt][nj][r] = 0.f;

    int a_row = wm * 64 + (lane & 15);                       // + mt*16
    int a_kb  = (lane >> 4) << 4;                            // + ks*32 (bytes)
    int b_row = wn * 32 + ((lane >> 4) << 3) + (lane & 7);   // + nt*16
    int b_kb  = ((lane >> 3) & 1) << 4;                      // + ks*32 (bytes)

    const int KT = K >> 5;
    load_stage(0, 0);
    load_stage(1, 1);
    int buf = 0;
    for (int kt = 0; kt < KT; ++kt) {
        if (kt + 2 < KT) {
            int nb = buf + 2; if (nb >= NSTAGE) nb -= NSTAGE;
            load_stage(kt + 2, nb);
            CP_WAIT(2);
        } else if (kt + 1 < KT) {
            CP_WAIT(1);
        } else {
            CP_WAIT(0);
        }
        __syncthreads();

        uint32_t base = sb + buf * STAGE_SZ;
        #pragma unroll
        for (int ks = 0; ks < 2; ++ks) {                     // two k16 sub-slices
            uint32_t kboff = ks * 32;
            uint32_t a[4][4], b[4][2];
            #pragma unroll
            for (int mt = 0; mt < 4; ++mt) {
                uint32_t off = (uint32_t)((a_row + mt * 16) * ROWB) + a_kb + kboff;
                ldsm_x4(a[mt], base + off);
            }
            #pragma unroll
            for (int nt = 0; nt < 2; ++nt) {
                uint32_t off = (uint32_t)((b_row + nt * 16) * ROWB) + b_kb + kboff;
                uint32_t t0[4];
                ldsm_x4(t0, base + ARR_SZ + off);
                b[nt*2][0]   = t0[0]; b[nt*2][1]   = t0[1];
                b[nt*2+1][0] = t0[2]; b[nt*2+1][1] = t0[3];
            }
            #pragma unroll
            for (int mt = 0; mt < 4; ++mt)
                #pragma unroll
                for (int nj = 0; nj < 4; ++nj)
                    mma_bf16(c[mt][nj], a[mt], b[nj]);
        }
        __syncthreads();
        if (++buf == NSTAGE) buf = 0;
    }

    // epilogue
    #pragma unroll
    for (int mt = 0; mt < 4; ++mt) {
        #pragma unroll
        for (int nj = 0; nj < 4; ++nj) {
            int row0 = bm + wm * 64 + mt * 16 + (lane >> 2);
            int col  = bn + wn * 32 + nj * 8 + (lane & 3) * 2;
            float b0 = bias[col], b1 = bias[col + 1];
            float v[4] = { c[mt][nj][0] + b0, c[mt][nj][1] + b1,
                           c[mt][nj][2] + b0, c[mt][nj][3] + b1 };
            if (EPI == EPI_SOFTPLUS) {
                #pragma unroll
                for (int r = 0; r < 4; ++r) {
                    float sp = fmaxf(v[r], 0.f) + log1pf(expf(-fabsf(v[r])));
                    v[r] = fminf(fmaxf(sp, 1e-4f), 10.0f);
                }
            } else if (EPI == EPI_RESID) {
                long p0 = (long)row0 * N + col, p1 = (long)(row0 + 8) * N + col;
                v[0] += resid[p0]; v[1] += resid[p0 + 1];
                v[2] += resid[p1]; v[3] += resid[p1 + 1];
            }
            *(float2*)(C + (long)row0 * N + col)       = make_float2(v[0], v[1]);
            *(float2*)(C + (long)(row0 + 8) * N + col) = make_float2(v[2], v[3]);
        }
    }
}

// ---------------------------------------------------------------------------
// Causal depthwise conv(4) + bias + SiLU; emits fp32 + bf16
// ---------------------------------------------------------------------------
__global__ void conv_silu_kernel(const float* __restrict__ conv_w,
                                 const float* __restrict__ conv_b) {
    int idx = blockIdx.x * blockDim.x + threadIdx.x;
    if (idx >= BATCH * LSEQ * DINNER) return;
    int c = idx & (DINNER - 1);
    int t = (idx >> 11) & (LSEQ - 1);
    int b = idx >> 21;
    const float* xin = g_xz + (long)(b * LSEQ) * (2 * DINNER) + c;
    float acc = conv_b[c];
    #pragma unroll
    for (int j = 0; j < DCONV; ++j) {
        int tt = t - (DCONV - 1) + j;
        if (tt >= 0) acc = fmaf(xin[(long)tt * (2 * DINNER)], conv_w[c * DCONV + j], acc);
    }
    float sig = 1.0f / (1.0f + expf(-acc));
    float yv = acc * sig;
    long o = (long)(b * LSEQ + t) * DINNER + c;
    g_xc[o] = yv;
    g_xc_h[o] = __float2bfloat16(yv);
}

// ---------------------------------------------------------------------------
// x_proj: BC = xc @ W[32,2048]^T + b. Block = 32 rows x 32 outs, K-tiled smem.
// ---------------------------------------------------------------------------
__global__ __launch_bounds__(256)
void xproj_kernel(const float* __restrict__ W, const float* __restrict__ bias) {
    __shared__ float Xs[32][65];
    __shared__ float Ws[32][65];
    int tid = threadIdx.x;
    int row0 = blockIdx.x * 32;
    int rg = (tid >> 5) * 4;
    int n  = tid & 31;
    float acc[4] = {0.f, 0.f, 0.f, 0.f};
    for (int k0 = 0; k0 < DINNER; k0 += 64) {
        #pragma unroll
        for (int i = 0; i < 2; ++i) {
            int id = tid * 2 + i;
            int r = id >> 4, c4 = (id & 15) * 4;
            float4 xv = *(const float4*)(g_xc + (long)(row0 + r) * DINNER + k0 + c4);
            Xs[r][c4] = xv.x; Xs[r][c4+1] = xv.y; Xs[r][c4+2] = xv.z; Xs[r][c4+3] = xv.w;
            float4 wv = *(const float4*)(W + (long)r * DINNER + k0 + c4);
            Ws[r][c4] = wv.x; Ws[r][c4+1] = wv.y; Ws[r][c4+2] = wv.z; Ws[r][c4+3] = wv.w;
        }
        __syncthreads();
        #pragma unroll
        for (int kk = 0; kk < 64; ++kk) {
            float w = Ws[n][kk];
            #pragma unroll
            for (int i = 0; i < 4; ++i) acc[i] = fmaf(Xs[rg + i][kk], w, acc[i]);
        }
        __syncthreads();
    }
    float bv = bias[n];
    #pragma unroll
    for (int i = 0; i < 4; ++i)
        g_bc[(long)(row0 + rg + i) * 32 + n] = acc[i] + bv;
}

// ---------------------------------------------------------------------------
// Selective scan + z-gate; emits bf16 gated y.
// Warp = 2 channels (16 lanes = 16 states each).
// ---------------------------------------------------------------------------
__global__ void scan_kernel(const float* __restrict__ A_log,
                            const float* __restrict__ Dvec) {
    int gw   = (blockIdx.x * blockDim.x + threadIdx.x) >> 5;
    int lane = threadIdx.x & 31;
    int s    = lane & 15;
    int half = lane >> 4;
    int b  = gw >> 10;
    int cp = gw & 1023;
    int c  = cp * 2 + half;

    float a  = -expf(A_log[c * DSTATE + s]);
    float Dc = Dvec[c];
    float h = 0.f;

    const float* dl  = g_delta + (long)b * LSEQ * DINNER;
    const float* xcb = g_xc    + (long)b * LSEQ * DINNER;
    const float* bcb = g_bc    + (long)b * LSEQ * 2 * DSTATE;
    const float* zb  = g_xz    + (long)b * LSEQ * 2 * DINNER + DINNER;

    for (int t = 0; t < LSEQ; ++t) {
        float d  = dl [(long)t * DINNER + c];
        float xv = xcb[(long)t * DINNER + c];
        float Bv = bcb[t * 32 + s];
        float Cv = bcb[t * 32 + 16 + s];
        float da = expf(fminf(fmaxf(d * a, -10.0f), 0.0f));
        h = fmaf(da, h, d * Bv * xv);
        if ((t & 15) == 15) {
            float ss = h * h;
            ss += __shfl_xor_sync(0xffffffffu, ss, 8);
            ss += __shfl_xor_sync(0xffffffffu, ss, 4);
            ss += __shfl_xor_sync(0xffffffffu, ss, 2);
            ss += __shfl_xor_sync(0xffffffffu, ss, 1);
            float hn = fmaxf(sqrtf(ss), 1e-6f);
            if (hn > 10.0f) h *= 10.0f / hn;
        }
        float p = Cv * h;
        p += __shfl_xor_sync(0xffffffffu, p, 8);
        p += __shfl_xor_sync(0xffffffffu, p, 4);
        p += __shfl_xor_sync(0xffffffffu, p, 2);
        p += __shfl_xor_sync(0xffffffffu, p, 1);
        if (s == 0) {
            float yv = p + Dc * xv;
            float z  = zb[(long)t * (2 * DINNER) + c];
            yv *= z / (1.0f + expf(-z));
            long o = (long)b * LSEQ * DINNER + (long)t * DINNER + c;
            g_y_h[o] = __float2bfloat16(yv);
        }
    }
}

// ---------------------------------------------------------------------------
// Launch
// ---------------------------------------------------------------------------
extern "C" void kernel_launch(void* const* d_in, const int* in_sizes, int n_in,
                              void* d_out, int out_size) {
    const float* x             = (const float*)d_in[0];
    const float* in_proj_w     = (const float*)d_in[1];
    const float* in_proj_b     = (const float*)d_in[2];
    const float* conv_w        = (const float*)d_in[3];
    const float* conv_b        = (const float*)d_in[4];
    const float* x_proj_w      = (const float*)d_in[5];
    const float* x_proj_b      = (const float*)d_in[6];
    const float* dt_proj_w     = (const float*)d_in[7];
    const float* dt_proj_b     = (const float*)d_in[8];
    const float* A_log         = (const float*)d_in[9];
    const float* Dvec          = (const float*)d_in[10];
    const float* out_proj_w    = (const float*)d_in[11];
    const float* out_proj_b    = (const float*)d_in[12];
    const float* in_norm_alpha = (const float*)d_in[13];
    const float* in_norm_bias  = (const float*)d_in[14];
    const float* norm_alpha    = (const float*)d_in[15];
    const float* norm_bias     = (const float*)d_in[16];
    float* out = (float*)d_out;

    __nv_bfloat16 *xn_h, *wi_h, *wd_h, *wo_h, *xc_h, *y_h;
    float *xz, *delta, *obuf;
    cudaGetSymbolAddress((void**)&xn_h, g_xn_h);
    cudaGetSymbolAddress((void**)&wi_h, g_wi_h);
    cudaGetSymbolAddress((void**)&wd_h, g_wd_h);
    cudaGetSymbolAddress((void**)&wo_h, g_wo_h);
    cudaGetSymbolAddress((void**)&xc_h, g_xc_h);
    cudaGetSymbolAddress((void**)&y_h,  g_y_h);
    cudaGetSymbolAddress((void**)&xz,    g_xz);
    cudaGetSymbolAddress((void**)&delta, g_delta);
    cudaGetSymbolAddress((void**)&obuf,  g_out);

    cudaFuncSetAttribute(gemm_hmma<EPI_BIAS>,     cudaFuncAttributeMaxDynamicSharedMemorySize, GEMM_SMEM);
    cudaFuncSetAttribute(gemm_hmma<EPI_SOFTPLUS>, cudaFuncAttributeMaxDynamicSharedMemorySize, GEMM_SMEM);
    cudaFuncSetAttribute(gemm_hmma<EPI_RESID>,    cudaFuncAttributeMaxDynamicSharedMemorySize, GEMM_SMEM);

    // weight converts
    cvt_kernel<<<(2 * DINNER * DMODEL / 4 + 255) / 256, 256>>>(in_proj_w,  wi_h, 2 * DINNER * DMODEL / 4);
    cvt_kernel<<<(DINNER * DINNER / 4 + 255) / 256, 256>>>(dt_proj_w,  wd_h, DINNER * DINNER / 4);
    cvt_kernel<<<(DMODEL * DINNER / 4 + 255) / 256, 256>>>(out_proj_w, wo_h, DMODEL * DINNER / 4);

    // 1. input layernorm -> bf16
    ln_kernel<1><<<ROWS, 256>>>(x, in_norm_alpha, in_norm_bias, nullptr, xn_h);

    // 2. in_proj (2048 x 4096 x 1024)
    gemm_hmma<EPI_BIAS><<<dim3(32, 16), 256, GEMM_SMEM>>>(
        xn_h, wi_h, in_proj_b, nullptr, xz, ROWS, 2 * DINNER, DMODEL);

    // 3. conv + silu
    conv_silu_kernel<<<(BATCH * LSEQ * DINNER) / 256, 256>>>(conv_w, conv_b);

    // 4. x_proj -> B,C
    xproj_kernel<<<ROWS / 32, 256>>>(x_proj_w, x_proj_b);

    // 5. dt_proj + softplus + clip (2048 x 2048 x 2048)
    gemm_hmma<EPI_SOFTPLUS><<<dim3(16, 16), 256, GEMM_SMEM>>>(
        xc_h, wd_h, dt_proj_b, nullptr, delta, ROWS, DINNER, DINNER);

    // 6. selective scan + z gate
    scan_kernel<<<256, 256>>>(A_log, Dvec);

    // 7. out_proj + residual (2048 x 1024 x 2048)
    gemm_hmma<EPI_RESID><<<dim3(8, 16), 256, GEMM_SMEM>>>(
        y_h, wo_h, out_proj_b, x, obuf, ROWS, DMODEL, DINNER);

    // 8. final layernorm -> d_out
    ln_kernel<0><<<ROWS, 256>>>(obuf, norm_alpha, norm_bias, out, nullptr);
}

// round 6
// speedup vs baseline: 1.9010x; 1.0060x over previous
#include <cuda_runtime.h>
#include <cuda_bf16.h>
#include <math.h>
#include <stdint.h>

// ---------------------------------------------------------------------------
// Shapes (fixed): B=2, L=1024, d_model=1024, d_state=16, d_conv=4, d_inner=2048
// ---------------------------------------------------------------------------
#define BATCH    2
#define LSEQ     1024
#define DMODEL   1024
#define DSTATE   16
#define DCONV    4
#define DINNER   2048
#define ROWS     (BATCH * LSEQ)

// ---------------------------------------------------------------------------
// Scratch (device globals; no allocation allowed)
// ---------------------------------------------------------------------------
__device__ __nv_bfloat16 g_xn_h[ROWS * DMODEL];
__device__ __nv_bfloat16 g_wi_h[2 * DINNER * DMODEL];
__device__ __nv_bfloat16 g_wd_h[DINNER * DINNER];
__device__ __nv_bfloat16 g_wo_h[DMODEL * DINNER];
__device__ __nv_bfloat16 g_xc_h[ROWS * DINNER];
__device__ __nv_bfloat16 g_y_h [ROWS * DINNER];
__device__ float g_xz   [ROWS * 2 * DINNER];
__device__ float g_xc   [ROWS * DINNER];
__device__ float g_bc   [ROWS * 2 * DSTATE];
__device__ float g_delta[ROWS * DINNER];
__device__ float g_out  [ROWS * DMODEL];

// ---------------------------------------------------------------------------
// PTX helpers (plain sm_80+ features only)
// ---------------------------------------------------------------------------
__device__ __forceinline__ uint32_t smem_to_u32(const void* p) {
    uint32_t a;
    asm("{ .reg .u64 t; cvta.to.shared.u64 t, %1; cvt.u32.u64 %0, t; }" : "=r"(a) : "l"(p));
    return a;
}
#define CP_ASYNC16(dst, src) \
    asm volatile("cp.async.cg.shared.global [%0], [%1], 16;" :: "r"(dst), "l"(src))
#define CP_COMMIT() asm volatile("cp.async.commit_group;" ::: "memory")
#define CP_WAIT(n)  asm volatile("cp.async.wait_group %0;" :: "n"(n) : "memory")

__device__ __forceinline__ void ldsm_x4(uint32_t* r, uint32_t addr) {
    asm volatile("ldmatrix.sync.aligned.m8n8.x4.shared.b16 {%0,%1,%2,%3}, [%4];"
        : "=r"(r[0]), "=r"(r[1]), "=r"(r[2]), "=r"(r[3]) : "r"(addr));
}
__device__ __forceinline__ void mma_bf16(float* c, const uint32_t* a, const uint32_t* b) {
    asm volatile(
        "mma.sync.aligned.m16n8k16.row.col.f32.bf16.bf16.f32 "
        "{%0,%1,%2,%3}, {%4,%5,%6,%7}, {%8,%9}, {%0,%1,%2,%3};"
        : "+f"(c[0]), "+f"(c[1]), "+f"(c[2]), "+f"(c[3])
        : "r"(a[0]), "r"(a[1]), "r"(a[2]), "r"(a[3]), "r"(b[0]), "r"(b[1]));
}

// ---------------------------------------------------------------------------
// LayerNorm (ddof=1 std, eps on std). SPLIT=1 emits bf16, else fp32.
// ---------------------------------------------------------------------------
__device__ __forceinline__ float warp_sum32(float v) {
    #pragma unroll
    for (int m = 16; m > 0; m >>= 1) v += __shfl_xor_sync(0xffffffffu, v, m);
    return v;
}

template<int SPLIT>
__global__ void ln_kernel(const float* __restrict__ X,
                          const float* __restrict__ alpha,
                          const float* __restrict__ beta,
                          float* __restrict__ Y,
                          __nv_bfloat16* __restrict__ Yh) {
    __shared__ float sh[2][8];
    int row = blockIdx.x;
    int tid = threadIdx.x;
    const float* xr = X + (long)row * DMODEL;
    float4 xv = *(const float4*)(xr + tid * 4);
    float s  = xv.x + xv.y + xv.z + xv.w;
    float ss = xv.x*xv.x + xv.y*xv.y + xv.z*xv.z + xv.w*xv.w;
    s = warp_sum32(s); ss = warp_sum32(ss);
    if ((tid & 31) == 0) { sh[0][tid >> 5] = s; sh[1][tid >> 5] = ss; }
    __syncthreads();
    float S = 0.f, SS = 0.f;
    #pragma unroll
    for (int w = 0; w < 8; ++w) { S += sh[0][w]; SS += sh[1][w]; }
    float mean = S * (1.0f / (float)DMODEL);
    float var  = fmaxf((SS - (float)DMODEL * mean * mean) * (1.0f / (float)(DMODEL - 1)), 0.f);
    float inv  = 1.0f / (sqrtf(var) + 1e-6f);
    float4 av = *(const float4*)(alpha + tid * 4);
    float4 bv = *(const float4*)(beta  + tid * 4);
    float o[4];
    o[0] = av.x * (xv.x - mean) * inv + bv.x;
    o[1] = av.y * (xv.y - mean) * inv + bv.y;
    o[2] = av.z * (xv.z - mean) * inv + bv.z;
    o[3] = av.w * (xv.w - mean) * inv + bv.w;
    long base = (long)row * DMODEL + tid * 4;
    if (SPLIT) {
        __nv_bfloat16 h[4];
        #pragma unroll
        for (int j = 0; j < 4; ++j) h[j] = __float2bfloat16(o[j]);
        *(uint2*)(Yh + base) = *(uint2*)h;
    } else {
        *(float4*)(Y + base) = make_float4(o[0], o[1], o[2], o[3]);
    }
}

// ---------------------------------------------------------------------------
// fp32 -> bf16 convert (weights)
// ---------------------------------------------------------------------------
__global__ void cvt_kernel(const float* __restrict__ X,
                           __nv_bfloat16* __restrict__ H, int n4) {
    int i = blockIdx.x * blockDim.x + threadIdx.x;
    if (i >= n4) return;
    float4 v = *(const float4*)(X + (long)i * 4);
    __nv_bfloat16 h[4] = { __float2bfloat16(v.x), __float2bfloat16(v.y),
                           __float2bfloat16(v.z), __float2bfloat16(v.w) };
    *(uint2*)(H + (long)i * 4) = *(uint2*)h;
}

// ---------------------------------------------------------------------------
// Single-pass bf16 HMMA GEMM: C[M,N] = A[M,K] @ B[N,K]^T (+ epilogue)
// Block tile 128x128, BK=32, 8 warps (2m x 4n), warp tile 64x32.
// 4-stage cp.async pipeline, 2 CTAs/SM, software-pipelined ldmatrix.
// EPI: 0 bias, 1 bias+softplus+clip, 2 bias+residual
// ---------------------------------------------------------------------------
#define EPI_BIAS     0
#define EPI_SOFTPLUS 1
#define EPI_RESID    2
#define ROWB      80                       // padded row bytes (32 bf16 -> 80B)
#define ARR_SZ    (128 * ROWB)             // 10240 B per operand
#define STAGE_SZ  (2 * ARR_SZ)             // 20480 B per stage
#define NSTAGE    4
#define GEMM_SMEM (NSTAGE * STAGE_SZ)      // 81920 B

template<int EPI>
__global__ __launch_bounds__(256, 2)
void gemm_hmma(const __nv_bfloat16* __restrict__ A, const __nv_bfloat16* __restrict__ B,
               const float* __restrict__ bias, const float* __restrict__ resid,
               float* __restrict__ C, int M, int N, int K) {
    extern __shared__ char smem[];
    uint32_t sb = smem_to_u32(smem);
    int tid  = threadIdx.x;
    int lane = tid & 31;
    int wid  = tid >> 5;
    int wm   = wid & 1;                    // 2 m-groups of 64
    int wn   = wid >> 1;                   // 4 n-groups of 32
    int bm = blockIdx.y * 128, bn = blockIdx.x * 128;

    const __nv_bfloat16* srcs[2] = { A + (long)bm * K, B + (long)bn * K };

    // per-thread load slots (4 x 16B chunks per stage)
    int s_arr[4], s_row[4], s_c[4];
    #pragma unroll
    for (int i = 0; i < 4; ++i) {
        int id = tid + i * 256;            // 0..1023
        s_arr[i] = id >> 9;
        int rem = id & 511;
        s_row[i] = rem >> 2;
        s_c[i]   = rem & 3;
    }

    auto load_stage = [&](int kt, int buf) {
        #pragma unroll
        for (int i = 0; i < 4; ++i) {
            uint32_t dst = sb + buf * STAGE_SZ + s_arr[i] * ARR_SZ
                         + s_row[i] * ROWB + s_c[i] * 16;
            const __nv_bfloat16* src = srcs[s_arr[i]] + (long)s_row[i] * K
                                     + kt * 32 + s_c[i] * 8;
            CP_ASYNC16(dst, src);
        }
        CP_COMMIT();
    };

    float c[4][4][4];
    #pragma unroll
    for (int mt = 0; mt < 4; ++mt)
        #pragma unroll
        for (int nj = 0; nj < 4; ++nj)
            #pragma unroll
            for (int r = 0; r < 4; ++r) c[mt][nj][r] = 0.f;

    int a_row = wm * 64 + (lane & 15);                       // + mt*16
    int a_kb  = (lane >> 4) << 4;                            // + ks*32 (bytes)
    int b_row = wn * 32 + ((lane >> 4) << 3) + (lane & 7);   // + nt*16
    int b_kb  = ((lane >> 3) & 1) << 4;                      // + ks*32 (bytes)

    auto load_frags = [&](uint32_t base, int ks, uint32_t a[4][4], uint32_t b[4][2]) {
        uint32_t kboff = ks * 32;
        #pragma unroll
        for (int mt = 0; mt < 4; ++mt) {
            uint32_t off = (uint32_t)((a_row + mt * 16) * ROWB) + a_kb + kboff;
            ldsm_x4(a[mt], base + off);
        }
        #pragma unroll
        for (int nt = 0; nt < 2; ++nt) {
            uint32_t off = (uint32_t)((b_row + nt * 16) * ROWB) + b_kb + kboff;
            uint32_t t0[4];
            ldsm_x4(t0, base + ARR_SZ + off);
            b[nt*2][0]   = t0[0]; b[nt*2][1]   = t0[1];
            b[nt*2+1][0] = t0[2]; b[nt*2+1][1] = t0[3];
        }
    };
    auto do_mmas = [&](uint32_t a[4][4], uint32_t b[4][2]) {
        #pragma unroll
        for (int mt = 0; mt < 4; ++mt)
            #pragma unroll
            for (int nj = 0; nj < 4; ++nj)
                mma_bf16(c[mt][nj], a[mt], b[nj]);
    };

    const int KT = K >> 5;
    load_stage(0, 0);
    load_stage(1, 1);
    load_stage(2, 2);
    int buf = 0;
    for (int kt = 0; kt < KT; ++kt) {
        if (kt + 3 < KT) {
            int nb = buf + 3; if (nb >= NSTAGE) nb -= NSTAGE;
            load_stage(kt + 3, nb);
            CP_WAIT(3);
        } else if (kt + 2 < KT) { CP_WAIT(2); }
        else if (kt + 1 < KT)   { CP_WAIT(1); }
        else                    { CP_WAIT(0); }
        __syncthreads();

        uint32_t base = sb + buf * STAGE_SZ;
        // software-pipelined: frag loads for ks+1 issued before MMAs of ks
        uint32_t a0[4][4], b0[4][2], a1[4][4], b1[4][2];
        load_frags(base, 0, a0, b0);
        load_frags(base, 1, a1, b1);
        do_mmas(a0, b0);
        do_mmas(a1, b1);
        __syncthreads();
        if (++buf == NSTAGE) buf = 0;
    }

    // epilogue
    #pragma unroll
    for (int mt = 0; mt < 4; ++mt) {
        #pragma unroll
        for (int nj = 0; nj < 4; ++nj) {
            int row0 = bm + wm * 64 + mt * 16 + (lane >> 2);
            int col  = bn + wn * 32 + nj * 8 + (lane & 3) * 2;
            float b0 = bias[col], b1 = bias[col + 1];
            float v[4] = { c[mt][nj][0] + b0, c[mt][nj][1] + b1,
                           c[mt][nj][2] + b0, c[mt][nj][3] + b1 };
            if (EPI == EPI_SOFTPLUS) {
                #pragma unroll
                for (int r = 0; r < 4; ++r) {
                    float sp = fmaxf(v[r], 0.f) + log1pf(expf(-fabsf(v[r])));
                    v[r] = fminf(fmaxf(sp, 1e-4f), 10.0f);
                }
            } else if (EPI == EPI_RESID) {
                long p0 = (long)row0 * N + col, p1 = (long)(row0 + 8) * N + col;
                v[0] += resid[p0]; v[1] += resid[p0 + 1];
                v[2] += resid[p1]; v[3] += resid[p1 + 1];
            }
            *(float2*)(C + (long)row0 * N + col)       = make_float2(v[0], v[1]);
            *(float2*)(C + (long)(row0 + 8) * N + col) = make_float2(v[2], v[3]);
        }
    }
}

// ---------------------------------------------------------------------------
// Causal depthwise conv(4) + bias + SiLU; emits fp32 + bf16
// ---------------------------------------------------------------------------
__global__ void conv_silu_kernel(const float* __restrict__ conv_w,
                                 const float* __restrict__ conv_b) {
    int idx = blockIdx.x * blockDim.x + threadIdx.x;
    if (idx >= BATCH * LSEQ * DINNER) return;
    int c = idx & (DINNER - 1);
    int t = (idx >> 11) & (LSEQ - 1);
    int b = idx >> 21;
    const float* xin = g_xz + (long)(b * LSEQ) * (2 * DINNER) + c;
    float acc = conv_b[c];
    #pragma unroll
    for (int j = 0; j < DCONV; ++j) {
        int tt = t - (DCONV - 1) + j;
        if (tt >= 0) acc = fmaf(xin[(long)tt * (2 * DINNER)], conv_w[c * DCONV + j], acc);
    }
    float sig = 1.0f / (1.0f + expf(-acc));
    float yv = acc * sig;
    long o = (long)(b * LSEQ + t) * DINNER + c;
    g_xc[o] = yv;
    g_xc_h[o] = __float2bfloat16(yv);
}

// ---------------------------------------------------------------------------
// x_proj: BC = xc @ W[32,2048]^T + b. Block = 32 rows x 32 outs, K-tiled smem.
// ---------------------------------------------------------------------------
__global__ __launch_bounds__(256)
void xproj_kernel(const float* __restrict__ W, const float* __restrict__ bias) {
    __shared__ float Xs[32][65];
    __shared__ float Ws[32][65];
    int tid = threadIdx.x;
    int row0 = blockIdx.x * 32;
    int rg = (tid >> 5) * 4;
    int n  = tid & 31;
    float acc[4] = {0.f, 0.f, 0.f, 0.f};
    for (int k0 = 0; k0 < DINNER; k0 += 64) {
        #pragma unroll
        for (int i = 0; i < 2; ++i) {
            int id = tid * 2 + i;
            int r = id >> 4, c4 = (id & 15) * 4;
            float4 xv = *(const float4*)(g_xc + (long)(row0 + r) * DINNER + k0 + c4);
            Xs[r][c4] = xv.x; Xs[r][c4+1] = xv.y; Xs[r][c4+2] = xv.z; Xs[r][c4+3] = xv.w;
            float4 wv = *(const float4*)(W + (long)r * DINNER + k0 + c4);
            Ws[r][c4] = wv.x; Ws[r][c4+1] = wv.y; Ws[r][c4+2] = wv.z; Ws[r][c4+3] = wv.w;
        }
        __syncthreads();
        #pragma unroll
        for (int kk = 0; kk < 64; ++kk) {
            float w = Ws[n][kk];
            #pragma unroll
            for (int i = 0; i < 4; ++i) acc[i] = fmaf(Xs[rg + i][kk], w, acc[i]);
        }
        __syncthreads();
    }
    float bv = bias[n];
    #pragma unroll
    for (int i = 0; i < 4; ++i)
        g_bc[(long)(row0 + rg + i) * 32 + n] = acc[i] + bv;
}

// ---------------------------------------------------------------------------
// Selective scan + z-gate; emits bf16 gated y.
// Warp = 2 channels (16 lanes = 16 states each).
// ---------------------------------------------------------------------------
__global__ void scan_kernel(const float* __restrict__ A_log,
                            const float* __restrict__ Dvec) {
    int gw   = (blockIdx.x * blockDim.x + threadIdx.x) >> 5;
    int lane = threadIdx.x & 31;
    int s    = lane & 15;
    int half = lane >> 4;
    int b  = gw >> 10;
    int cp = gw & 1023;
    int c  = cp * 2 + half;

    float a  = -expf(A_log[c * DSTATE + s]);
    float Dc = Dvec[c];
    float h = 0.f;

    const float* dl  = g_delta + (long)b * LSEQ * DINNER;
    const float* xcb = g_xc    + (long)b * LSEQ * DINNER;
    const float* bcb = g_bc    + (long)b * LSEQ * 2 * DSTATE;
    const float* zb  = g_xz    + (long)b * LSEQ * 2 * DINNER + DINNER;

    for (int t = 0; t < LSEQ; ++t) {
        float d  = dl [(long)t * DINNER + c];
        float xv = xcb[(long)t * DINNER + c];
        float Bv = bcb[t * 32 + s];
        float Cv = bcb[t * 32 + 16 + s];
        float da = expf(fminf(fmaxf(d * a, -10.0f), 0.0f));
        h = fmaf(da, h, d * Bv * xv);
        if ((t & 15) == 15) {
            float ss = h * h;
            ss += __shfl_xor_sync(0xffffffffu, ss, 8);
            ss += __shfl_xor_sync(0xffffffffu, ss, 4);
            ss += __shfl_xor_sync(0xffffffffu, ss, 2);
            ss += __shfl_xor_sync(0xffffffffu, ss, 1);
            float hn = fmaxf(sqrtf(ss), 1e-6f);
            if (hn > 10.0f) h *= 10.0f / hn;
        }
        float p = Cv * h;
        p += __shfl_xor_sync(0xffffffffu, p, 8);
        p += __shfl_xor_sync(0xffffffffu, p, 4);
        p += __shfl_xor_sync(0xffffffffu, p, 2);
        p += __shfl_xor_sync(0xffffffffu, p, 1);
        if (s == 0) {
            float yv = p + Dc * xv;
            float z  = zb[(long)t * (2 * DINNER) + c];
            yv *= z / (1.0f + expf(-z));
            long o = (long)b * LSEQ * DINNER + (long)t * DINNER + c;
            g_y_h[o] = __float2bfloat16(yv);
        }
    }
}

// ---------------------------------------------------------------------------
// Launch (ordered so in_proj GEMM lands at capture index 3)
// ---------------------------------------------------------------------------
extern "C" void kernel_launch(void* const* d_in, const int* in_sizes, int n_in,
                              void* d_out, int out_size) {
    const float* x             = (const float*)d_in[0];
    const float* in_proj_w     = (const float*)d_in[1];
    const float* in_proj_b     = (const float*)d_in[2];
    const float* conv_w        = (const float*)d_in[3];
    const float* conv_b        = (const float*)d_in[4];
    const float* x_proj_w      = (const float*)d_in[5];
    const float* x_proj_b      = (const float*)d_in[6];
    const float* dt_proj_w     = (const float*)d_in[7];
    const float* dt_proj_b     = (const float*)d_in[8];
    const float* A_log         = (const float*)d_in[9];
    const float* Dvec          = (const float*)d_in[10];
    const float* out_proj_w    = (const float*)d_in[11];
    const float* out_proj_b    = (const float*)d_in[12];
    const float* in_norm_alpha = (const float*)d_in[13];
    const float* in_norm_bias  = (const float*)d_in[14];
    const float* norm_alpha    = (const float*)d_in[15];
    const float* norm_bias     = (const float*)d_in[16];
    float* out = (float*)d_out;

    __nv_bfloat16 *xn_h, *wi_h, *wd_h, *wo_h, *xc_h, *y_h;
    float *xz, *delta, *obuf;
    cudaGetSymbolAddress((void**)&xn_h, g_xn_h);
    cudaGetSymbolAddress((void**)&wi_h, g_wi_h);
    cudaGetSymbolAddress((void**)&wd_h, g_wd_h);
    cudaGetSymbolAddress((void**)&wo_h, g_wo_h);
    cudaGetSymbolAddress((void**)&xc_h, g_xc_h);
    cudaGetSymbolAddress((void**)&y_h,  g_y_h);
    cudaGetSymbolAddress((void**)&xz,    g_xz);
    cudaGetSymbolAddress((void**)&delta, g_delta);
    cudaGetSymbolAddress((void**)&obuf,  g_out);

    cudaFuncSetAttribute(gemm_hmma<EPI_BIAS>,     cudaFuncAttributeMaxDynamicSharedMemorySize, GEMM_SMEM);
    cudaFuncSetAttribute(gemm_hmma<EPI_SOFTPLUS>, cudaFuncAttributeMaxDynamicSharedMemorySize, GEMM_SMEM);
    cudaFuncSetAttribute(gemm_hmma<EPI_RESID>,    cudaFuncAttributeMaxDynamicSharedMemorySize, GEMM_SMEM);

    // 0. input layernorm -> bf16
    ln_kernel<1><<<ROWS, 256>>>(x, in_norm_alpha, in_norm_bias, nullptr, xn_h);
    // 1-2. weight converts needed before first two GEMMs
    cvt_kernel<<<(2 * DINNER * DMODEL / 4 + 255) / 256, 256>>>(in_proj_w, wi_h, 2 * DINNER * DMODEL / 4);
    cvt_kernel<<<(DINNER * DINNER / 4 + 255) / 256, 256>>>(dt_proj_w, wd_h, DINNER * DINNER / 4);
    // 3. in_proj (2048 x 4096 x 1024)  <-- ncu capture slot
    gemm_hmma<EPI_BIAS><<<dim3(32, 16), 256, GEMM_SMEM>>>(
        xn_h, wi_h, in_proj_b, nullptr, xz, ROWS, 2 * DINNER, DMODEL);
    // 4. conv + silu
    conv_silu_kernel<<<(BATCH * LSEQ * DINNER) / 256, 256>>>(conv_w, conv_b);
    // 5. x_proj -> B,C
    xproj_kernel<<<ROWS / 32, 256>>>(x_proj_w, x_proj_b);
    // 6. dt_proj + softplus + clip (2048 x 2048 x 2048)
    gemm_hmma<EPI_SOFTPLUS><<<dim3(16, 16), 256, GEMM_SMEM>>>(
        xc_h, wd_h, dt_proj_b, nullptr, delta, ROWS, DINNER, DINNER);
    // 7. selective scan + z gate
    scan_kernel<<<256, 256>>>(A_log, Dvec);
    // 8. out_proj weight convert (only needed before gemm_out)
    cvt_kernel<<<(DMODEL * DINNER / 4 + 255) / 256, 256>>>(out_proj_w, wo_h, DMODEL * DINNER / 4);
    // 9. out_proj + residual (2048 x 1024 x 2048)
    gemm_hmma<EPI_RESID><<<dim3(8, 16), 256, GEMM_SMEM>>>(
        y_h, wo_h, out_proj_b, x, obuf, ROWS, DMODEL, DINNER);
    // 10. final layernorm -> d_out
    ln_kernel<0><<<ROWS, 256>>>(obuf, norm_alpha, norm_bias, out, nullptr);
}

// round 7
// speedup vs baseline: 2.9999x; 1.5781x over previous
#include <cuda_runtime.h>
#include <cuda_bf16.h>
#include <math.h>
#include <stdint.h>

// ---------------------------------------------------------------------------
// Shapes (fixed): B=2, L=1024, d_model=1024, d_state=16, d_conv=4, d_inner=2048
// ---------------------------------------------------------------------------
#define BATCH    2
#define LSEQ     1024
#define DMODEL   1024
#define DSTATE   16
#define DCONV    4
#define DINNER   2048
#define ROWS     (BATCH * LSEQ)

// ---------------------------------------------------------------------------
// Scratch (device globals; no allocation allowed)
// ---------------------------------------------------------------------------
__device__ __nv_bfloat16 g_xn_h[ROWS * DMODEL];
__device__ __nv_bfloat16 g_wi_h[2 * DINNER * DMODEL];
__device__ __nv_bfloat16 g_wd_h[DINNER * DINNER];
__device__ __nv_bfloat16 g_wo_h[DMODEL * DINNER];
__device__ __nv_bfloat16 g_xc_h[ROWS * DINNER];
__device__ __nv_bfloat16 g_y_h [ROWS * DINNER];
__device__ float g_xz   [ROWS * 2 * DINNER];
__device__ float g_xc   [ROWS * DINNER];
__device__ float g_bc   [ROWS * 2 * DSTATE];    // interleaved [t][s][{B,C}]
__device__ float g_delta[ROWS * DINNER];
__device__ float g_out  [ROWS * DMODEL];

// ---------------------------------------------------------------------------
// PTX helpers (plain sm_80+ features only)
// ---------------------------------------------------------------------------
__device__ __forceinline__ uint32_t smem_to_u32(const void* p) {
    uint32_t a;
    asm("{ .reg .u64 t; cvta.to.shared.u64 t, %1; cvt.u32.u64 %0, t; }" : "=r"(a) : "l"(p));
    return a;
}
#define CP_ASYNC16(dst, src) \
    asm volatile("cp.async.cg.shared.global [%0], [%1], 16;" :: "r"(dst), "l"(src))
#define CP_COMMIT() asm volatile("cp.async.commit_group;" ::: "memory")
#define CP_WAIT(n)  asm volatile("cp.async.wait_group %0;" :: "n"(n) : "memory")

__device__ __forceinline__ void ldsm_x4(uint32_t* r, uint32_t addr) {
    asm volatile("ldmatrix.sync.aligned.m8n8.x4.shared.b16 {%0,%1,%2,%3}, [%4];"
        : "=r"(r[0]), "=r"(r[1]), "=r"(r[2]), "=r"(r[3]) : "r"(addr));
}
__device__ __forceinline__ void mma_bf16(float* c, const uint32_t* a, const uint32_t* b) {
    asm volatile(
        "mma.sync.aligned.m16n8k16.row.col.f32.bf16.bf16.f32 "
        "{%0,%1,%2,%3}, {%4,%5,%6,%7}, {%8,%9}, {%0,%1,%2,%3};"
        : "+f"(c[0]), "+f"(c[1]), "+f"(c[2]), "+f"(c[3])
        : "r"(a[0]), "r"(a[1]), "r"(a[2]), "r"(a[3]), "r"(b[0]), "r"(b[1]));
}

// ---------------------------------------------------------------------------
// LayerNorm (ddof=1 std, eps on std). SPLIT=1 emits bf16, else fp32.
// ---------------------------------------------------------------------------
__device__ __forceinline__ float warp_sum32(float v) {
    #pragma unroll
    for (int m = 16; m > 0; m >>= 1) v += __shfl_xor_sync(0xffffffffu, v, m);
    return v;
}

template<int SPLIT>
__global__ void ln_kernel(const float* __restrict__ X,
                          const float* __restrict__ alpha,
                          const float* __restrict__ beta,
                          float* __restrict__ Y,
                          __nv_bfloat16* __restrict__ Yh) {
    __shared__ float sh[2][8];
    int row = blockIdx.x;
    int tid = threadIdx.x;
    const float* xr = X + (long)row * DMODEL;
    float4 xv = *(const float4*)(xr + tid * 4);
    float s  = xv.x + xv.y + xv.z + xv.w;
    float ss = xv.x*xv.x + xv.y*xv.y + xv.z*xv.z + xv.w*xv.w;
    s = warp_sum32(s); ss = warp_sum32(ss);
    if ((tid & 31) == 0) { sh[0][tid >> 5] = s; sh[1][tid >> 5] = ss; }
    __syncthreads();
    float S = 0.f, SS = 0.f;
    #pragma unroll
    for (int w = 0; w < 8; ++w) { S += sh[0][w]; SS += sh[1][w]; }
    float mean = S * (1.0f / (float)DMODEL);
    float var  = fmaxf((SS - (float)DMODEL * mean * mean) * (1.0f / (float)(DMODEL - 1)), 0.f);
    float inv  = 1.0f / (sqrtf(var) + 1e-6f);
    float4 av = *(const float4*)(alpha + tid * 4);
    float4 bv = *(const float4*)(beta  + tid * 4);
    float o[4];
    o[0] = av.x * (xv.x - mean) * inv + bv.x;
    o[1] = av.y * (xv.y - mean) * inv + bv.y;
    o[2] = av.z * (xv.z - mean) * inv + bv.z;
    o[3] = av.w * (xv.w - mean) * inv + bv.w;
    long base = (long)row * DMODEL + tid * 4;
    if (SPLIT) {
        __nv_bfloat16 h[4];
        #pragma unroll
        for (int j = 0; j < 4; ++j) h[j] = __float2bfloat16(o[j]);
        *(uint2*)(Yh + base) = *(uint2*)h;
    } else {
        *(float4*)(Y + base) = make_float4(o[0], o[1], o[2], o[3]);
    }
}

// ---------------------------------------------------------------------------
// fp32 -> bf16 convert (weights)
// ---------------------------------------------------------------------------
__global__ void cvt_kernel(const float* __restrict__ X,
                           __nv_bfloat16* __restrict__ H, int n4) {
    int i = blockIdx.x * blockDim.x + threadIdx.x;
    if (i >= n4) return;
    float4 v = *(const float4*)(X + (long)i * 4);
    __nv_bfloat16 h[4] = { __float2bfloat16(v.x), __float2bfloat16(v.y),
                           __float2bfloat16(v.z), __float2bfloat16(v.w) };
    *(uint2*)(H + (long)i * 4) = *(uint2*)h;
}

// ---------------------------------------------------------------------------
// Single-pass bf16 HMMA GEMM (same as R6: 4-stage cp.async, 2 CTA/SM)
// ---------------------------------------------------------------------------
#define EPI_BIAS     0
#define EPI_SOFTPLUS 1
#define EPI_RESID    2
#define ROWB      80
#define ARR_SZ    (128 * ROWB)
#define STAGE_SZ  (2 * ARR_SZ)
#define NSTAGE    4
#define GEMM_SMEM (NSTAGE * STAGE_SZ)

template<int EPI>
__global__ __launch_bounds__(256, 2)
void gemm_hmma(const __nv_bfloat16* __restrict__ A, const __nv_bfloat16* __restrict__ B,
               const float* __restrict__ bias, const float* __restrict__ resid,
               float* __restrict__ C, int M, int N, int K) {
    extern __shared__ char smem[];
    uint32_t sb = smem_to_u32(smem);
    int tid  = threadIdx.x;
    int lane = tid & 31;
    int wid  = tid >> 5;
    int wm   = wid & 1;
    int wn   = wid >> 1;
    int bm = blockIdx.y * 128, bn = blockIdx.x * 128;

    const __nv_bfloat16* srcs[2] = { A + (long)bm * K, B + (long)bn * K };

    int s_arr[4], s_row[4], s_c[4];
    #pragma unroll
    for (int i = 0; i < 4; ++i) {
        int id = tid + i * 256;
        s_arr[i] = id >> 9;
        int rem = id & 511;
        s_row[i] = rem >> 2;
        s_c[i]   = rem & 3;
    }

    auto load_stage = [&](int kt, int buf) {
        #pragma unroll
        for (int i = 0; i < 4; ++i) {
            uint32_t dst = sb + buf * STAGE_SZ + s_arr[i] * ARR_SZ
                         + s_row[i] * ROWB + s_c[i] * 16;
            const __nv_bfloat16* src = srcs[s_arr[i]] + (long)s_row[i] * K
                                     + kt * 32 + s_c[i] * 8;
            CP_ASYNC16(dst, src);
        }
        CP_COMMIT();
    };

    float c[4][4][4];
    #pragma unroll
    for (int mt = 0; mt < 4; ++mt)
        #pragma unroll
        for (int nj = 0; nj < 4; ++nj)
            #pragma unroll
            for (int r = 0; r < 4; ++r) c[mt][nj][r] = 0.f;

    int a_row = wm * 64 + (lane & 15);
    int a_kb  = (lane >> 4) << 4;
    int b_row = wn * 32 + ((lane >> 4) << 3) + (lane & 7);
    int b_kb  = ((lane >> 3) & 1) << 4;

    auto load_frags = [&](uint32_t base, int ks, uint32_t a[4][4], uint32_t b[4][2]) {
        uint32_t kboff = ks * 32;
        #pragma unroll
        for (int mt = 0; mt < 4; ++mt) {
            uint32_t off = (uint32_t)((a_row + mt * 16) * ROWB) + a_kb + kboff;
            ldsm_x4(a[mt], base + off);
        }
        #pragma unroll
        for (int nt = 0; nt < 2; ++nt) {
            uint32_t off = (uint32_t)((b_row + nt * 16) * ROWB) + b_kb + kboff;
            uint32_t t0[4];
            ldsm_x4(t0, base + ARR_SZ + off);
            b[nt*2][0]   = t0[0]; b[nt*2][1]   = t0[1];
            b[nt*2+1][0] = t0[2]; b[nt*2+1][1] = t0[3];
        }
    };
    auto do_mmas = [&](uint32_t a[4][4], uint32_t b[4][2]) {
        #pragma unroll
        for (int mt = 0; mt < 4; ++mt)
            #pragma unroll
            for (int nj = 0; nj < 4; ++nj)
                mma_bf16(c[mt][nj], a[mt], b[nj]);
    };

    const int KT = K >> 5;
    load_stage(0, 0);
    load_stage(1, 1);
    load_stage(2, 2);
    int buf = 0;
    for (int kt = 0; kt < KT; ++kt) {
        if (kt + 3 < KT) {
            int nb = buf + 3; if (nb >= NSTAGE) nb -= NSTAGE;
            load_stage(kt + 3, nb);
            CP_WAIT(3);
        } else if (kt + 2 < KT) { CP_WAIT(2); }
        else if (kt + 1 < KT)   { CP_WAIT(1); }
        else                    { CP_WAIT(0); }
        __syncthreads();

        uint32_t base = sb + buf * STAGE_SZ;
        uint32_t a0[4][4], b0[4][2], a1[4][4], b1[4][2];
        load_frags(base, 0, a0, b0);
        load_frags(base, 1, a1, b1);
        do_mmas(a0, b0);
        do_mmas(a1, b1);
        __syncthreads();
        if (++buf == NSTAGE) buf = 0;
    }

    #pragma unroll
    for (int mt = 0; mt < 4; ++mt) {
        #pragma unroll
        for (int nj = 0; nj < 4; ++nj) {
            int row0 = bm + wm * 64 + mt * 16 + (lane >> 2);
            int col  = bn + wn * 32 + nj * 8 + (lane & 3) * 2;
            float b0 = bias[col], b1 = bias[col + 1];
            float v[4] = { c[mt][nj][0] + b0, c[mt][nj][1] + b1,
                           c[mt][nj][2] + b0, c[mt][nj][3] + b1 };
            if (EPI == EPI_SOFTPLUS) {
                #pragma unroll
                for (int r = 0; r < 4; ++r) {
                    float sp = fmaxf(v[r], 0.f) + log1pf(expf(-fabsf(v[r])));
                    v[r] = fminf(fmaxf(sp, 1e-4f), 10.0f);
                }
            } else if (EPI == EPI_RESID) {
                long p0 = (long)row0 * N + col, p1 = (long)(row0 + 8) * N + col;
                v[0] += resid[p0]; v[1] += resid[p0 + 1];
                v[2] += resid[p1]; v[3] += resid[p1 + 1];
            }
            *(float2*)(C + (long)row0 * N + col)       = make_float2(v[0], v[1]);
            *(float2*)(C + (long)(row0 + 8) * N + col) = make_float2(v[2], v[3]);
        }
    }
}

// ---------------------------------------------------------------------------
// Causal depthwise conv(4) + bias + SiLU; emits fp32 + bf16
// ---------------------------------------------------------------------------
__global__ void conv_silu_kernel(const float* __restrict__ conv_w,
                                 const float* __restrict__ conv_b) {
    int idx = blockIdx.x * blockDim.x + threadIdx.x;
    if (idx >= BATCH * LSEQ * DINNER) return;
    int c = idx & (DINNER - 1);
    int t = (idx >> 11) & (LSEQ - 1);
    int b = idx >> 21;
    const float* xin = g_xz + (long)(b * LSEQ) * (2 * DINNER) + c;
    float acc = conv_b[c];
    #pragma unroll
    for (int j = 0; j < DCONV; ++j) {
        int tt = t - (DCONV - 1) + j;
        if (tt >= 0) acc = fmaf(xin[(long)tt * (2 * DINNER)], conv_w[c * DCONV + j], acc);
    }
    float sig = 1.0f / (1.0f + expf(-acc));
    float yv = acc * sig;
    long o = (long)(b * LSEQ + t) * DINNER + c;
    g_xc[o] = yv;
    g_xc_h[o] = __float2bfloat16(yv);
}

// ---------------------------------------------------------------------------
// x_proj: BC = xc @ W[32,2048]^T + b, written INTERLEAVED: [row][s][{B,C}]
// ---------------------------------------------------------------------------
__global__ __launch_bounds__(256)
void xproj_kernel(const float* __restrict__ W, const float* __restrict__ bias) {
    __shared__ float Xs[32][65];
    __shared__ float Ws[32][65];
    int tid = threadIdx.x;
    int row0 = blockIdx.x * 32;
    int rg = (tid >> 5) * 4;
    int n  = tid & 31;
    float acc[4] = {0.f, 0.f, 0.f, 0.f};
    for (int k0 = 0; k0 < DINNER; k0 += 64) {
        #pragma unroll
        for (int i = 0; i < 2; ++i) {
            int id = tid * 2 + i;
            int r = id >> 4, c4 = (id & 15) * 4;
            float4 xv = *(const float4*)(g_xc + (long)(row0 + r) * DINNER + k0 + c4);
            Xs[r][c4] = xv.x; Xs[r][c4+1] = xv.y; Xs[r][c4+2] = xv.z; Xs[r][c4+3] = xv.w;
            float4 wv = *(const float4*)(W + (long)r * DINNER + k0 + c4);
            Ws[r][c4] = wv.x; Ws[r][c4+1] = wv.y; Ws[r][c4+2] = wv.z; Ws[r][c4+3] = wv.w;
        }
        __syncthreads();
        #pragma unroll
        for (int kk = 0; kk < 64; ++kk) {
            float w = Ws[n][kk];
            #pragma unroll
            for (int i = 0; i < 4; ++i) acc[i] = fmaf(Xs[rg + i][kk], w, acc[i]);
        }
        __syncthreads();
    }
    float bv = bias[n];
    int off = (n & 15) * 2 + (n >> 4);          // interleave B,C per state
    #pragma unroll
    for (int i = 0; i < 4; ++i)
        g_bc[(long)(row0 + rg + i) * 32 + off] = acc[i] + bv;
}

// ---------------------------------------------------------------------------
// Selective scan + z-gate; software-prefetched, unroll-16, float2 BC loads.
// Warp = 2 channels (16 lanes = 16 states each).
// ---------------------------------------------------------------------------
__global__ void scan_kernel(const float* __restrict__ A_log,
                            const float* __restrict__ Dvec) {
    int gw   = (blockIdx.x * blockDim.x + threadIdx.x) >> 5;
    int lane = threadIdx.x & 31;
    int s    = lane & 15;
    int half = lane >> 4;
    int b  = gw >> 10;
    int cp = gw & 1023;
    int c  = cp * 2 + half;

    float a  = -expf(A_log[c * DSTATE + s]);
    float Dc = Dvec[c];
    float h = 0.f;

    const float* dl  = g_delta + (long)b * LSEQ * DINNER + c;
    const float* xcb = g_xc    + (long)b * LSEQ * DINNER + c;
    const float* bcb = g_bc    + (long)b * LSEQ * 32 + s * 2;
    const float* zb  = g_xz    + (long)b * LSEQ * 2 * DINNER + DINNER + c;
    __nv_bfloat16* yb = g_y_h  + (long)b * LSEQ * DINNER + c;

    // prefetch t=0
    float  d_n  = dl[0];
    float  x_n  = xcb[0];
    float2 bc_n = *(const float2*)bcb;
    float  z_n  = zb[0];

    for (int t0 = 0; t0 < LSEQ; t0 += 16) {
        #pragma unroll
        for (int j = 0; j < 16; ++j) {
            int t = t0 + j;
            float  d  = d_n;
            float  xv = x_n;
            float2 bc = bc_n;
            float  z  = z_n;
            // issue next-iteration loads before any dependent math / shfl
            int tn = (t + 1 < LSEQ) ? t + 1 : t;
            d_n  = dl[(long)tn * DINNER];
            x_n  = xcb[(long)tn * DINNER];
            bc_n = *(const float2*)(bcb + tn * 32);
            z_n  = zb[(long)tn * 2 * DINNER];

            float da = __expf(fminf(fmaxf(d * a, -10.0f), 0.0f));
            h = fmaf(da, h, d * bc.x * xv);
            if (j == 15) {
                float ss = h * h;
                ss += __shfl_xor_sync(0xffffffffu, ss, 8);
                ss += __shfl_xor_sync(0xffffffffu, ss, 4);
                ss += __shfl_xor_sync(0xffffffffu, ss, 2);
                ss += __shfl_xor_sync(0xffffffffu, ss, 1);
                if (ss > 100.0f) h *= 10.0f * rsqrtf(ss);
            }
            float p = bc.y * h;
            p += __shfl_xor_sync(0xffffffffu, p, 8);
            p += __shfl_xor_sync(0xffffffffu, p, 4);
            p += __shfl_xor_sync(0xffffffffu, p, 2);
            p += __shfl_xor_sync(0xffffffffu, p, 1);
            if (s == 0) {
                float yv = p + Dc * xv;
                yv *= z / (1.0f + __expf(-z));
                yb[(long)t * DINNER] = __float2bfloat16(yv);
            }
        }
    }
}

// ---------------------------------------------------------------------------
// Launch (in_proj GEMM stays at capture index 3)
// ---------------------------------------------------------------------------
extern "C" void kernel_launch(void* const* d_in, const int* in_sizes, int n_in,
                              void* d_out, int out_size) {
    const float* x             = (const float*)d_in[0];
    const float* in_proj_w     = (const float*)d_in[1];
    const float* in_proj_b     = (const float*)d_in[2];
    const float* conv_w        = (const float*)d_in[3];
    const float* conv_b        = (const float*)d_in[4];
    const float* x_proj_w      = (const float*)d_in[5];
    const float* x_proj_b      = (const float*)d_in[6];
    const float* dt_proj_w     = (const float*)d_in[7];
    const float* dt_proj_b     = (const float*)d_in[8];
    const float* A_log         = (const float*)d_in[9];
    const float* Dvec          = (const float*)d_in[10];
    const float* out_proj_w    = (const float*)d_in[11];
    const float* out_proj_b    = (const float*)d_in[12];
    const float* in_norm_alpha = (const float*)d_in[13];
    const float* in_norm_bias  = (const float*)d_in[14];
    const float* norm_alpha    = (const float*)d_in[15];
    const float* norm_bias     = (const float*)d_in[16];
    float* out = (float*)d_out;

    __nv_bfloat16 *xn_h, *wi_h, *wd_h, *wo_h, *xc_h, *y_h;
    float *xz, *delta, *obuf;
    cudaGetSymbolAddress((void**)&xn_h, g_xn_h);
    cudaGetSymbolAddress((void**)&wi_h, g_wi_h);
    cudaGetSymbolAddress((void**)&wd_h, g_wd_h);
    cudaGetSymbolAddress((void**)&wo_h, g_wo_h);
    cudaGetSymbolAddress((void**)&xc_h, g_xc_h);
    cudaGetSymbolAddress((void**)&y_h,  g_y_h);
    cudaGetSymbolAddress((void**)&xz,    g_xz);
    cudaGetSymbolAddress((void**)&delta, g_delta);
    cudaGetSymbolAddress((void**)&obuf,  g_out);

    cudaFuncSetAttribute(gemm_hmma<EPI_BIAS>,     cudaFuncAttributeMaxDynamicSharedMemorySize, GEMM_SMEM);
    cudaFuncSetAttribute(gemm_hmma<EPI_SOFTPLUS>, cudaFuncAttributeMaxDynamicSharedMemorySize, GEMM_SMEM);
    cudaFuncSetAttribute(gemm_hmma<EPI_RESID>,    cudaFuncAttributeMaxDynamicSharedMemorySize, GEMM_SMEM);

    // 0. input layernorm -> bf16
    ln_kernel<1><<<ROWS, 256>>>(x, in_norm_alpha, in_norm_bias, nullptr, xn_h);
    // 1-2. weight converts for first two GEMMs
    cvt_kernel<<<(2 * DINNER * DMODEL / 4 + 255) / 256, 256>>>(in_proj_w, wi_h, 2 * DINNER * DMODEL / 4);
    cvt_kernel<<<(DINNER * DINNER / 4 + 255) / 256, 256>>>(dt_proj_w, wd_h, DINNER * DINNER / 4);
    // 3. in_proj (2048 x 4096 x 1024)  <-- ncu capture slot
    gemm_hmma<EPI_BIAS><<<dim3(32, 16), 256, GEMM_SMEM>>>(
        xn_h, wi_h, in_proj_b, nullptr, xz, ROWS, 2 * DINNER, DMODEL);
    // 4. conv + silu
    conv_silu_kernel<<<(BATCH * LSEQ * DINNER) / 256, 256>>>(conv_w, conv_b);
    // 5. x_proj -> interleaved B,C
    xproj_kernel<<<ROWS / 32, 256>>>(x_proj_w, x_proj_b);
    // 6. dt_proj + softplus + clip (2048 x 2048 x 2048)
    gemm_hmma<EPI_SOFTPLUS><<<dim3(16, 16), 256, GEMM_SMEM>>>(
        xc_h, wd_h, dt_proj_b, nullptr, delta, ROWS, DINNER, DINNER);
    // 7. selective scan + z gate
    scan_kernel<<<256, 256>>>(A_log, Dvec);
    // 8. out_proj weight convert
    cvt_kernel<<<(DMODEL * DINNER / 4 + 255) / 256, 256>>>(out_proj_w, wo_h, DMODEL * DINNER / 4);
    // 9. out_proj + residual (2048 x 1024 x 2048)
    gemm_hmma<EPI_RESID><<<dim3(8, 16), 256, GEMM_SMEM>>>(
        y_h, wo_h, out_proj_b, x, obuf, ROWS, DMODEL, DINNER);
    // 10. final layernorm -> d_out
    ln_kernel<0><<<ROWS, 256>>>(obuf, norm_alpha, norm_bias, out, nullptr);
}

// round 8
// speedup vs baseline: 3.7811x; 1.2604x over previous
#include <cuda_runtime.h>
#include <cuda_bf16.h>
#include <math.h>
#include <stdint.h>

// ---------------------------------------------------------------------------
// Shapes (fixed): B=2, L=1024, d_model=1024, d_state=16, d_conv=4, d_inner=2048
// ---------------------------------------------------------------------------
#define BATCH    2
#define LSEQ     1024
#define DMODEL   1024
#define DSTATE   16
#define DCONV    4
#define DINNER   2048
#define ROWS     (BATCH * LSEQ)

// ---------------------------------------------------------------------------
// Scratch (device globals; no allocation allowed)
// ---------------------------------------------------------------------------
__device__ __nv_bfloat16 g_xn_h[ROWS * DMODEL];
__device__ __nv_bfloat16 g_wi_h[2 * DINNER * DMODEL];
__device__ __nv_bfloat16 g_wd_h[DINNER * DINNER];
__device__ __nv_bfloat16 g_wo_h[DMODEL * DINNER];
__device__ __nv_bfloat16 g_xc_h[ROWS * DINNER];
__device__ __nv_bfloat16 g_y_h [ROWS * DINNER];
__device__ float g_xz   [ROWS * 2 * DINNER];
__device__ float g_xc   [ROWS * DINNER];
__device__ float g_bc   [ROWS * 2 * DSTATE];    // interleaved [t][s][{B,C}]
__device__ float g_delta[ROWS * DINNER];
__device__ float g_out  [ROWS * DMODEL];

// ---------------------------------------------------------------------------
// PTX helpers (plain sm_80+ features only)
// ---------------------------------------------------------------------------
__device__ __forceinline__ uint32_t smem_to_u32(const void* p) {
    uint32_t a;
    asm("{ .reg .u64 t; cvta.to.shared.u64 t, %1; cvt.u32.u64 %0, t; }" : "=r"(a) : "l"(p));
    return a;
}
#define CP_ASYNC16(dst, src) \
    asm volatile("cp.async.cg.shared.global [%0], [%1], 16;" :: "r"(dst), "l"(src))
#define CP_COMMIT() asm volatile("cp.async.commit_group;" ::: "memory")
#define CP_WAIT(n)  asm volatile("cp.async.wait_group %0;" :: "n"(n) : "memory")

__device__ __forceinline__ void ldsm_x4(uint32_t* r, uint32_t addr) {
    asm volatile("ldmatrix.sync.aligned.m8n8.x4.shared.b16 {%0,%1,%2,%3}, [%4];"
        : "=r"(r[0]), "=r"(r[1]), "=r"(r[2]), "=r"(r[3]) : "r"(addr));
}
__device__ __forceinline__ void mma_bf16(float* c, const uint32_t* a, const uint32_t* b) {
    asm volatile(
        "mma.sync.aligned.m16n8k16.row.col.f32.bf16.bf16.f32 "
        "{%0,%1,%2,%3}, {%4,%5,%6,%7}, {%8,%9}, {%0,%1,%2,%3};"
        : "+f"(c[0]), "+f"(c[1]), "+f"(c[2]), "+f"(c[3])
        : "r"(a[0]), "r"(a[1]), "r"(a[2]), "r"(a[3]), "r"(b[0]), "r"(b[1]));
}

// ---------------------------------------------------------------------------
// LayerNorm (ddof=1 std, eps on std). SPLIT=1 emits bf16, else fp32.
// ---------------------------------------------------------------------------
__device__ __forceinline__ float warp_sum32(float v) {
    #pragma unroll
    for (int m = 16; m > 0; m >>= 1) v += __shfl_xor_sync(0xffffffffu, v, m);
    return v;
}

template<int SPLIT>
__global__ void ln_kernel(const float* __restrict__ X,
                          const float* __restrict__ alpha,
                          const float* __restrict__ beta,
                          float* __restrict__ Y,
                          __nv_bfloat16* __restrict__ Yh) {
    __shared__ float sh[2][8];
    int row = blockIdx.x;
    int tid = threadIdx.x;
    const float* xr = X + (long)row * DMODEL;
    float4 xv = *(const float4*)(xr + tid * 4);
    float s  = xv.x + xv.y + xv.z + xv.w;
    float ss = xv.x*xv.x + xv.y*xv.y + xv.z*xv.z + xv.w*xv.w;
    s = warp_sum32(s); ss = warp_sum32(ss);
    if ((tid & 31) == 0) { sh[0][tid >> 5] = s; sh[1][tid >> 5] = ss; }
    __syncthreads();
    float S = 0.f, SS = 0.f;
    #pragma unroll
    for (int w = 0; w < 8; ++w) { S += sh[0][w]; SS += sh[1][w]; }
    float mean = S * (1.0f / (float)DMODEL);
    float var  = fmaxf((SS - (float)DMODEL * mean * mean) * (1.0f / (float)(DMODEL - 1)), 0.f);
    float inv  = 1.0f / (sqrtf(var) + 1e-6f);
    float4 av = *(const float4*)(alpha + tid * 4);
    float4 bv = *(const float4*)(beta  + tid * 4);
    float o[4];
    o[0] = av.x * (xv.x - mean) * inv + bv.x;
    o[1] = av.y * (xv.y - mean) * inv + bv.y;
    o[2] = av.z * (xv.z - mean) * inv + bv.z;
    o[3] = av.w * (xv.w - mean) * inv + bv.w;
    long base = (long)row * DMODEL + tid * 4;
    if (SPLIT) {
        __nv_bfloat16 h[4];
        #pragma unroll
        for (int j = 0; j < 4; ++j) h[j] = __float2bfloat16(o[j]);
        *(uint2*)(Yh + base) = *(uint2*)h;
    } else {
        *(float4*)(Y + base) = make_float4(o[0], o[1], o[2], o[3]);
    }
}

// ---------------------------------------------------------------------------
// fp32 -> bf16 convert (weights)
// ---------------------------------------------------------------------------
__global__ void cvt_kernel(const float* __restrict__ X,
                           __nv_bfloat16* __restrict__ H, int n4) {
    int i = blockIdx.x * blockDim.x + threadIdx.x;
    if (i >= n4) return;
    float4 v = *(const float4*)(X + (long)i * 4);
    __nv_bfloat16 h[4] = { __float2bfloat16(v.x), __float2bfloat16(v.y),
                           __float2bfloat16(v.z), __float2bfloat16(v.w) };
    *(uint2*)(H + (long)i * 4) = *(uint2*)h;
}

// ---------------------------------------------------------------------------
// Single-pass bf16 HMMA GEMM (4-stage cp.async, 2 CTA/SM)
// ---------------------------------------------------------------------------
#define EPI_BIAS     0
#define EPI_SOFTPLUS 1
#define EPI_RESID    2
#define ROWB      80
#define ARR_SZ    (128 * ROWB)
#define STAGE_SZ  (2 * ARR_SZ)
#define NSTAGE    4
#define GEMM_SMEM (NSTAGE * STAGE_SZ)

template<int EPI>
__global__ __launch_bounds__(256, 2)
void gemm_hmma(const __nv_bfloat16* __restrict__ A, const __nv_bfloat16* __restrict__ B,
               const float* __restrict__ bias, const float* __restrict__ resid,
               float* __restrict__ C, int M, int N, int K) {
    extern __shared__ char smem[];
    uint32_t sb = smem_to_u32(smem);
    int tid  = threadIdx.x;
    int lane = tid & 31;
    int wid  = tid >> 5;
    int wm   = wid & 1;
    int wn   = wid >> 1;
    int bm = blockIdx.y * 128, bn = blockIdx.x * 128;

    const __nv_bfloat16* srcs[2] = { A + (long)bm * K, B + (long)bn * K };

    int s_arr[4], s_row[4], s_c[4];
    #pragma unroll
    for (int i = 0; i < 4; ++i) {
        int id = tid + i * 256;
        s_arr[i] = id >> 9;
        int rem = id & 511;
        s_row[i] = rem >> 2;
        s_c[i]   = rem & 3;
    }

    auto load_stage = [&](int kt, int buf) {
        #pragma unroll
        for (int i = 0; i < 4; ++i) {
            uint32_t dst = sb + buf * STAGE_SZ + s_arr[i] * ARR_SZ
                         + s_row[i] * ROWB + s_c[i] * 16;
            const __nv_bfloat16* src = srcs[s_arr[i]] + (long)s_row[i] * K
                                     + kt * 32 + s_c[i] * 8;
            CP_ASYNC16(dst, src);
        }
        CP_COMMIT();
    };

    float c[4][4][4];
    #pragma unroll
    for (int mt = 0; mt < 4; ++mt)
        #pragma unroll
        for (int nj = 0; nj < 4; ++nj)
            #pragma unroll
            for (int r = 0; r < 4; ++r) c[mt][nj][r] = 0.f;

    int a_row = wm * 64 + (lane & 15);
    int a_kb  = (lane >> 4) << 4;
    int b_row = wn * 32 + ((lane >> 4) << 3) + (lane & 7);
    int b_kb  = ((lane >> 3) & 1) << 4;

    auto load_frags = [&](uint32_t base, int ks, uint32_t a[4][4], uint32_t b[4][2]) {
        uint32_t kboff = ks * 32;
        #pragma unroll
        for (int mt = 0; mt < 4; ++mt) {
            uint32_t off = (uint32_t)((a_row + mt * 16) * ROWB) + a_kb + kboff;
            ldsm_x4(a[mt], base + off);
        }
        #pragma unroll
        for (int nt = 0; nt < 2; ++nt) {
            uint32_t off = (uint32_t)((b_row + nt * 16) * ROWB) + b_kb + kboff;
            uint32_t t0[4];
            ldsm_x4(t0, base + ARR_SZ + off);
            b[nt*2][0]   = t0[0]; b[nt*2][1]   = t0[1];
            b[nt*2+1][0] = t0[2]; b[nt*2+1][1] = t0[3];
        }
    };
    auto do_mmas = [&](uint32_t a[4][4], uint32_t b[4][2]) {
        #pragma unroll
        for (int mt = 0; mt < 4; ++mt)
            #pragma unroll
            for (int nj = 0; nj < 4; ++nj)
                mma_bf16(c[mt][nj], a[mt], b[nj]);
    };

    const int KT = K >> 5;
    load_stage(0, 0);
    load_stage(1, 1);
    load_stage(2, 2);
    int buf = 0;
    for (int kt = 0; kt < KT; ++kt) {
        if (kt + 3 < KT) {
            int nb = buf + 3; if (nb >= NSTAGE) nb -= NSTAGE;
            load_stage(kt + 3, nb);
            CP_WAIT(3);
        } else if (kt + 2 < KT) { CP_WAIT(2); }
        else if (kt + 1 < KT)   { CP_WAIT(1); }
        else                    { CP_WAIT(0); }
        __syncthreads();

        uint32_t base = sb + buf * STAGE_SZ;
        uint32_t a0[4][4], b0[4][2], a1[4][4], b1[4][2];
        load_frags(base, 0, a0, b0);
        load_frags(base, 1, a1, b1);
        do_mmas(a0, b0);
        do_mmas(a1, b1);
        __syncthreads();
        if (++buf == NSTAGE) buf = 0;
    }

    #pragma unroll
    for (int mt = 0; mt < 4; ++mt) {
        #pragma unroll
        for (int nj = 0; nj < 4; ++nj) {
            int row0 = bm + wm * 64 + mt * 16 + (lane >> 2);
            int col  = bn + wn * 32 + nj * 8 + (lane & 3) * 2;
            float b0 = bias[col], b1 = bias[col + 1];
            float v[4] = { c[mt][nj][0] + b0, c[mt][nj][1] + b1,
                           c[mt][nj][2] + b0, c[mt][nj][3] + b1 };
            if (EPI == EPI_SOFTPLUS) {
                #pragma unroll
                for (int r = 0; r < 4; ++r) {
                    float sp = fmaxf(v[r], 0.f) + log1pf(expf(-fabsf(v[r])));
                    v[r] = fminf(fmaxf(sp, 1e-4f), 10.0f);
                }
            } else if (EPI == EPI_RESID) {
                long p0 = (long)row0 * N + col, p1 = (long)(row0 + 8) * N + col;
                v[0] += resid[p0]; v[1] += resid[p0 + 1];
                v[2] += resid[p1]; v[3] += resid[p1 + 1];
            }
            *(float2*)(C + (long)row0 * N + col)       = make_float2(v[0], v[1]);
            *(float2*)(C + (long)(row0 + 8) * N + col) = make_float2(v[2], v[3]);
        }
    }
}

// ---------------------------------------------------------------------------
// Causal depthwise conv(4) + bias + SiLU; emits fp32 + bf16
// ---------------------------------------------------------------------------
__global__ void conv_silu_kernel(const float* __restrict__ conv_w,
                                 const float* __restrict__ conv_b) {
    int idx = blockIdx.x * blockDim.x + threadIdx.x;
    if (idx >= BATCH * LSEQ * DINNER) return;
    int c = idx & (DINNER - 1);
    int t = (idx >> 11) & (LSEQ - 1);
    int b = idx >> 21;
    const float* xin = g_xz + (long)(b * LSEQ) * (2 * DINNER) + c;
    float acc = conv_b[c];
    #pragma unroll
    for (int j = 0; j < DCONV; ++j) {
        int tt = t - (DCONV - 1) + j;
        if (tt >= 0) acc = fmaf(xin[(long)tt * (2 * DINNER)], conv_w[c * DCONV + j], acc);
    }
    float sig = 1.0f / (1.0f + expf(-acc));
    float yv = acc * sig;
    long o = (long)(b * LSEQ + t) * DINNER + c;
    g_xc[o] = yv;
    g_xc_h[o] = __float2bfloat16(yv);
}

// ---------------------------------------------------------------------------
// x_proj: BC = xc @ W[32,2048]^T + b, written INTERLEAVED: [row][s][{B,C}]
// ---------------------------------------------------------------------------
__global__ __launch_bounds__(256)
void xproj_kernel(const float* __restrict__ W, const float* __restrict__ bias) {
    __shared__ float Xs[32][65];
    __shared__ float Ws[32][65];
    int tid = threadIdx.x;
    int row0 = blockIdx.x * 32;
    int rg = (tid >> 5) * 4;
    int n  = tid & 31;
    float acc[4] = {0.f, 0.f, 0.f, 0.f};
    for (int k0 = 0; k0 < DINNER; k0 += 64) {
        #pragma unroll
        for (int i = 0; i < 2; ++i) {
            int id = tid * 2 + i;
            int r = id >> 4, c4 = (id & 15) * 4;
            float4 xv = *(const float4*)(g_xc + (long)(row0 + r) * DINNER + k0 + c4);
            Xs[r][c4] = xv.x; Xs[r][c4+1] = xv.y; Xs[r][c4+2] = xv.z; Xs[r][c4+3] = xv.w;
            float4 wv = *(const float4*)(W + (long)r * DINNER + k0 + c4);
            Ws[r][c4] = wv.x; Ws[r][c4+1] = wv.y; Ws[r][c4+2] = wv.z; Ws[r][c4+3] = wv.w;
        }
        __syncthreads();
        #pragma unroll
        for (int kk = 0; kk < 64; ++kk) {
            float w = Ws[n][kk];
            #pragma unroll
            for (int i = 0; i < 4; ++i) acc[i] = fmaf(Xs[rg + i][kk], w, acc[i]);
        }
        __syncthreads();
    }
    float bv = bias[n];
    int off = (n & 15) * 2 + (n >> 4);          // interleave B,C per state
    #pragma unroll
    for (int i = 0; i < 4; ++i)
        g_bc[(long)(row0 + rg + i) * 32 + off] = acc[i] + bv;
}

// ---------------------------------------------------------------------------
// Selective scan + z-gate; 4-deep register prefetch, unroll-16.
// Warp = 2 channels (16 lanes = 16 states each).
// ---------------------------------------------------------------------------
#define PFD 4   // prefetch depth (divides 16)
__global__ __launch_bounds__(128)
void scan_kernel(const float* __restrict__ A_log,
                 const float* __restrict__ Dvec) {
    int gw   = (blockIdx.x * blockDim.x + threadIdx.x) >> 5;   // 0..2047
    int lane = threadIdx.x & 31;
    int s    = lane & 15;
    int half = lane >> 4;
    int b  = gw >> 10;
    int cp = gw & 1023;
    int c  = cp * 2 + half;

    float a  = -expf(A_log[c * DSTATE + s]);     // strictly negative
    float Dc = Dvec[c];
    float h = 0.f;

    const float* dl  = g_delta + (long)b * LSEQ * DINNER + c;
    const float* xcb = g_xc    + (long)b * LSEQ * DINNER + c;
    const float* bcb = g_bc    + (long)b * LSEQ * 32 + s * 2;
    const float* zb  = g_xz    + (long)b * LSEQ * 2 * DINNER + DINNER + c;
    __nv_bfloat16* yb = g_y_h  + (long)b * LSEQ * DINNER + c;

    float  dbuf[PFD], xbuf[PFD], zbuf[PFD];
    float2 bcbuf[PFD];
    #pragma unroll
    for (int i = 0; i < PFD; ++i) {
        dbuf[i]  = dl [(long)i * DINNER];
        xbuf[i]  = xcb[(long)i * DINNER];
        bcbuf[i] = *(const float2*)(bcb + i * 32);
        zbuf[i]  = zb [(long)i * 2 * DINNER];
    }

    for (int t0 = 0; t0 < LSEQ; t0 += 16) {
        #pragma unroll
        for (int j = 0; j < 16; ++j) {
            int t = t0 + j;
            int slot = j & (PFD - 1);
            float  d  = dbuf[slot];
            float  xv = xbuf[slot];
            float2 bc = bcbuf[slot];
            float  z  = zbuf[slot];
            // refill slot with t+PFD (independent of everything below)
            int tn = t + PFD; if (tn >= LSEQ) tn = LSEQ - 1;
            dbuf[slot]  = dl [(long)tn * DINNER];
            xbuf[slot]  = xcb[(long)tn * DINNER];
            bcbuf[slot] = *(const float2*)(bcb + tn * 32);
            zbuf[slot]  = zb [(long)tn * 2 * DINNER];

            float da = __expf(fmaxf(d * a, -10.0f));   // d*a < 0 always
            h = fmaf(da, h, d * bc.x * xv);
            if (j == 15) {
                float ss = h * h;
                ss += __shfl_xor_sync(0xffffffffu, ss, 8);
                ss += __shfl_xor_sync(0xffffffffu, ss, 4);
                ss += __shfl_xor_sync(0xffffffffu, ss, 2);
                ss += __shfl_xor_sync(0xffffffffu, ss, 1);
                if (ss > 100.0f) h *= 10.0f * rsqrtf(ss);
            }
            float p = bc.y * h;
            p += __shfl_xor_sync(0xffffffffu, p, 8);
            p += __shfl_xor_sync(0xffffffffu, p, 4);
            p += __shfl_xor_sync(0xffffffffu, p, 2);
            p += __shfl_xor_sync(0xffffffffu, p, 1);
            if (s == 0) {
                float yv = p + Dc * xv;
                yv *= z / (1.0f + __expf(-z));
                yb[(long)t * DINNER] = __float2bfloat16(yv);
            }
        }
    }
}

// ---------------------------------------------------------------------------
// Launch (in_proj GEMM stays at capture index 3)
// ---------------------------------------------------------------------------
extern "C" void kernel_launch(void* const* d_in, const int* in_sizes, int n_in,
                              void* d_out, int out_size) {
    const float* x             = (const float*)d_in[0];
    const float* in_proj_w     = (const float*)d_in[1];
    const float* in_proj_b     = (const float*)d_in[2];
    const float* conv_w        = (const float*)d_in[3];
    const float* conv_b        = (const float*)d_in[4];
    const float* x_proj_w      = (const float*)d_in[5];
    const float* x_proj_b      = (const float*)d_in[6];
    const float* dt_proj_w     = (const float*)d_in[7];
    const float* dt_proj_b     = (const float*)d_in[8];
    const float* A_log         = (const float*)d_in[9];
    const float* Dvec          = (const float*)d_in[10];
    const float* out_proj_w    = (const float*)d_in[11];
    const float* out_proj_b    = (const float*)d_in[12];
    const float* in_norm_alpha = (const float*)d_in[13];
    const float* in_norm_bias  = (const float*)d_in[14];
    const float* norm_alpha    = (const float*)d_in[15];
    const float* norm_bias     = (const float*)d_in[16];
    float* out = (float*)d_out;

    __nv_bfloat16 *xn_h, *wi_h, *wd_h, *wo_h, *xc_h, *y_h;
    float *xz, *delta, *obuf;
    cudaGetSymbolAddress((void**)&xn_h, g_xn_h);
    cudaGetSymbolAddress((void**)&wi_h, g_wi_h);
    cudaGetSymbolAddress((void**)&wd_h, g_wd_h);
    cudaGetSymbolAddress((void**)&wo_h, g_wo_h);
    cudaGetSymbolAddress((void**)&xc_h, g_xc_h);
    cudaGetSymbolAddress((void**)&y_h,  g_y_h);
    cudaGetSymbolAddress((void**)&xz,    g_xz);
    cudaGetSymbolAddress((void**)&delta, g_delta);
    cudaGetSymbolAddress((void**)&obuf,  g_out);

    cudaFuncSetAttribute(gemm_hmma<EPI_BIAS>,     cudaFuncAttributeMaxDynamicSharedMemorySize, GEMM_SMEM);
    cudaFuncSetAttribute(gemm_hmma<EPI_SOFTPLUS>, cudaFuncAttributeMaxDynamicSharedMemorySize, GEMM_SMEM);
    cudaFuncSetAttribute(gemm_hmma<EPI_RESID>,    cudaFuncAttributeMaxDynamicSharedMemorySize, GEMM_SMEM);

    // 0. input layernorm -> bf16
    ln_kernel<1><<<ROWS, 256>>>(x, in_norm_alpha, in_norm_bias, nullptr, xn_h);
    // 1-2. weight converts for first two GEMMs
    cvt_kernel<<<(2 * DINNER * DMODEL / 4 + 255) / 256, 256>>>(in_proj_w, wi_h, 2 * DINNER * DMODEL / 4);
    cvt_kernel<<<(DINNER * DINNER / 4 + 255) / 256, 256>>>(dt_proj_w, wd_h, DINNER * DINNER / 4);
    // 3. in_proj (2048 x 4096 x 1024)  <-- ncu capture slot
    gemm_hmma<EPI_BIAS><<<dim3(32, 16), 256, GEMM_SMEM>>>(
        xn_h, wi_h, in_proj_b, nullptr, xz, ROWS, 2 * DINNER, DMODEL);
    // 4. conv + silu
    conv_silu_kernel<<<(BATCH * LSEQ * DINNER) / 256, 256>>>(conv_w, conv_b);
    // 5. x_proj -> interleaved B,C
    xproj_kernel<<<ROWS / 32, 256>>>(x_proj_w, x_proj_b);
    // 6. dt_proj + softplus + clip (2048 x 2048 x 2048)
    gemm_hmma<EPI_SOFTPLUS><<<dim3(16, 16), 256, GEMM_SMEM>>>(
        xc_h, wd_h, dt_proj_b, nullptr, delta, ROWS, DINNER, DINNER);
    // 7. selective scan + z gate (512 blocks x 4 warps)
    scan_kernel<<<512, 128>>>(A_log, Dvec);
    // 8. out_proj weight convert
    cvt_kernel<<<(DMODEL * DINNER / 4 + 255) / 256, 256>>>(out_proj_w, wo_h, DMODEL * DINNER / 4);
    // 9. out_proj + residual (2048 x 1024 x 2048)
    gemm_hmma<EPI_RESID><<<dim3(8, 16), 256, GEMM_SMEM>>>(
        y_h, wo_h, out_proj_b, x, obuf, ROWS, DMODEL, DINNER);
    // 10. final layernorm -> d_out
    ln_kernel<0><<<ROWS, 256>>>(obuf, norm_alpha, norm_bias, out, nullptr);
}

// round 9
// speedup vs baseline: 4.0220x; 1.0637x over previous
#include <cuda_runtime.h>
#include <cuda_bf16.h>
#include <math.h>
#include <stdint.h>

// ---------------------------------------------------------------------------
// Shapes (fixed): B=2, L=1024, d_model=1024, d_state=16, d_conv=4, d_inner=2048
// ---------------------------------------------------------------------------
#define BATCH    2
#define LSEQ     1024
#define DMODEL   1024
#define DSTATE   16
#define DCONV    4
#define DINNER   2048
#define ROWS     (BATCH * LSEQ)

// ---------------------------------------------------------------------------
// Scratch (device globals; no allocation allowed)
// ---------------------------------------------------------------------------
__device__ __nv_bfloat16 g_xn_h[ROWS * DMODEL];
__device__ __nv_bfloat16 g_wi_h[2 * DINNER * DMODEL];
__device__ __nv_bfloat16 g_wd_h[DINNER * DINNER];
__device__ __nv_bfloat16 g_wo_h[DMODEL * DINNER];
__device__ __nv_bfloat16 g_xc_h[ROWS * DINNER];
__device__ __nv_bfloat16 g_y_h [ROWS * DINNER];
__device__ float g_xz   [ROWS * 2 * DINNER];
__device__ float g_xc   [ROWS * DINNER];
__device__ float g_bc   [ROWS * 2 * DSTATE];    // interleaved [t][s][{B,C}]
__device__ float g_delta[ROWS * DINNER];
__device__ float g_out  [ROWS * DMODEL];

// ---------------------------------------------------------------------------
// PTX helpers (plain sm_80+ features only)
// ---------------------------------------------------------------------------
__device__ __forceinline__ uint32_t smem_to_u32(const void* p) {
    uint32_t a;
    asm("{ .reg .u64 t; cvta.to.shared.u64 t, %1; cvt.u32.u64 %0, t; }" : "=r"(a) : "l"(p));
    return a;
}
#define CP_ASYNC16(dst, src) \
    asm volatile("cp.async.cg.shared.global [%0], [%1], 16;" :: "r"(dst), "l"(src))
#define CP_COMMIT() asm volatile("cp.async.commit_group;" ::: "memory")
#define CP_WAIT(n)  asm volatile("cp.async.wait_group %0;" :: "n"(n) : "memory")

__device__ __forceinline__ void ldsm_x4(uint32_t* r, uint32_t addr) {
    asm volatile("ldmatrix.sync.aligned.m8n8.x4.shared.b16 {%0,%1,%2,%3}, [%4];"
        : "=r"(r[0]), "=r"(r[1]), "=r"(r[2]), "=r"(r[3]) : "r"(addr));
}
__device__ __forceinline__ void mma_bf16(float* c, const uint32_t* a, const uint32_t* b) {
    asm volatile(
        "mma.sync.aligned.m16n8k16.row.col.f32.bf16.bf16.f32 "
        "{%0,%1,%2,%3}, {%4,%5,%6,%7}, {%8,%9}, {%0,%1,%2,%3};"
        : "+f"(c[0]), "+f"(c[1]), "+f"(c[2]), "+f"(c[3])
        : "r"(a[0]), "r"(a[1]), "r"(a[2]), "r"(a[3]), "r"(b[0]), "r"(b[1]));
}

// ---------------------------------------------------------------------------
// LayerNorm (ddof=1 std, eps on std). SPLIT=1 emits bf16, else fp32.
// ---------------------------------------------------------------------------
__device__ __forceinline__ float warp_sum32(float v) {
    #pragma unroll
    for (int m = 16; m > 0; m >>= 1) v += __shfl_xor_sync(0xffffffffu, v, m);
    return v;
}

template<int SPLIT>
__global__ void ln_kernel(const float* __restrict__ X,
                          const float* __restrict__ alpha,
                          const float* __restrict__ beta,
                          float* __restrict__ Y,
                          __nv_bfloat16* __restrict__ Yh) {
    __shared__ float sh[2][8];
    int row = blockIdx.x;
    int tid = threadIdx.x;
    const float* xr = X + (long)row * DMODEL;
    float4 xv = *(const float4*)(xr + tid * 4);
    float s  = xv.x + xv.y + xv.z + xv.w;
    float ss = xv.x*xv.x + xv.y*xv.y + xv.z*xv.z + xv.w*xv.w;
    s = warp_sum32(s); ss = warp_sum32(ss);
    if ((tid & 31) == 0) { sh[0][tid >> 5] = s; sh[1][tid >> 5] = ss; }
    __syncthreads();
    float S = 0.f, SS = 0.f;
    #pragma unroll
    for (int w = 0; w < 8; ++w) { S += sh[0][w]; SS += sh[1][w]; }
    float mean = S * (1.0f / (float)DMODEL);
    float var  = fmaxf((SS - (float)DMODEL * mean * mean) * (1.0f / (float)(DMODEL - 1)), 0.f);
    float inv  = 1.0f / (sqrtf(var) + 1e-6f);
    float4 av = *(const float4*)(alpha + tid * 4);
    float4 bv = *(const float4*)(beta  + tid * 4);
    float o[4];
    o[0] = av.x * (xv.x - mean) * inv + bv.x;
    o[1] = av.y * (xv.y - mean) * inv + bv.y;
    o[2] = av.z * (xv.z - mean) * inv + bv.z;
    o[3] = av.w * (xv.w - mean) * inv + bv.w;
    long base = (long)row * DMODEL + tid * 4;
    if (SPLIT) {
        __nv_bfloat16 h[4];
        #pragma unroll
        for (int j = 0; j < 4; ++j) h[j] = __float2bfloat16(o[j]);
        *(uint2*)(Yh + base) = *(uint2*)h;
    } else {
        *(float4*)(Y + base) = make_float4(o[0], o[1], o[2], o[3]);
    }
}

// ---------------------------------------------------------------------------
// fp32 -> bf16 convert (weights)
// ---------------------------------------------------------------------------
__global__ void cvt_kernel(const float* __restrict__ X,
                           __nv_bfloat16* __restrict__ H, int n4) {
    int i = blockIdx.x * blockDim.x + threadIdx.x;
    if (i >= n4) return;
    float4 v = *(const float4*)(X + (long)i * 4);
    __nv_bfloat16 h[4] = { __float2bfloat16(v.x), __float2bfloat16(v.y),
                           __float2bfloat16(v.z), __float2bfloat16(v.w) };
    *(uint2*)(H + (long)i * 4) = *(uint2*)h;
}

// ---------------------------------------------------------------------------
// Single-pass bf16 HMMA GEMM (4-stage cp.async, 2 CTA/SM)
// ---------------------------------------------------------------------------
#define EPI_BIAS     0
#define EPI_SOFTPLUS 1
#define EPI_RESID    2
#define ROWB      80
#define ARR_SZ    (128 * ROWB)
#define STAGE_SZ  (2 * ARR_SZ)
#define NSTAGE    4
#define GEMM_SMEM (NSTAGE * STAGE_SZ)

template<int EPI>
__global__ __launch_bounds__(256, 2)
void gemm_hmma(const __nv_bfloat16* __restrict__ A, const __nv_bfloat16* __restrict__ B,
               const float* __restrict__ bias, const float* __restrict__ resid,
               float* __restrict__ C, int M, int N, int K) {
    extern __shared__ char smem[];
    uint32_t sb = smem_to_u32(smem);
    int tid  = threadIdx.x;
    int lane = tid & 31;
    int wid  = tid >> 5;
    int wm   = wid & 1;
    int wn   = wid >> 1;
    int bm = blockIdx.y * 128, bn = blockIdx.x * 128;

    const __nv_bfloat16* srcs[2] = { A + (long)bm * K, B + (long)bn * K };

    int s_arr[4], s_row[4], s_c[4];
    #pragma unroll
    for (int i = 0; i < 4; ++i) {
        int id = tid + i * 256;
        s_arr[i] = id >> 9;
        int rem = id & 511;
        s_row[i] = rem >> 2;
        s_c[i]   = rem & 3;
    }

    auto load_stage = [&](int kt, int buf) {
        #pragma unroll
        for (int i = 0; i < 4; ++i) {
            uint32_t dst = sb + buf * STAGE_SZ + s_arr[i] * ARR_SZ
                         + s_row[i] * ROWB + s_c[i] * 16;
            const __nv_bfloat16* src = srcs[s_arr[i]] + (long)s_row[i] * K
                                     + kt * 32 + s_c[i] * 8;
            CP_ASYNC16(dst, src);
        }
        CP_COMMIT();
    };

    float c[4][4][4];
    #pragma unroll
    for (int mt = 0; mt < 4; ++mt)
        #pragma unroll
        for (int nj = 0; nj < 4; ++nj)
            #pragma unroll
            for (int r = 0; r < 4; ++r) c[mt][nj][r] = 0.f;

    int a_row = wm * 64 + (lane & 15);
    int a_kb  = (lane >> 4) << 4;
    int b_row = wn * 32 + ((lane >> 4) << 3) + (lane & 7);
    int b_kb  = ((lane >> 3) & 1) << 4;

    auto load_frags = [&](uint32_t base, int ks, uint32_t a[4][4], uint32_t b[4][2]) {
        uint32_t kboff = ks * 32;
        #pragma unroll
        for (int mt = 0; mt < 4; ++mt) {
            uint32_t off = (uint32_t)((a_row + mt * 16) * ROWB) + a_kb + kboff;
            ldsm_x4(a[mt], base + off);
        }
        #pragma unroll
        for (int nt = 0; nt < 2; ++nt) {
            uint32_t off = (uint32_t)((b_row + nt * 16) * ROWB) + b_kb + kboff;
            uint32_t t0[4];
            ldsm_x4(t0, base + ARR_SZ + off);
            b[nt*2][0]   = t0[0]; b[nt*2][1]   = t0[1];
            b[nt*2+1][0] = t0[2]; b[nt*2+1][1] = t0[3];
        }
    };
    auto do_mmas = [&](uint32_t a[4][4], uint32_t b[4][2]) {
        #pragma unroll
        for (int mt = 0; mt < 4; ++mt)
            #pragma unroll
            for (int nj = 0; nj < 4; ++nj)
                mma_bf16(c[mt][nj], a[mt], b[nj]);
    };

    const int KT = K >> 5;
    load_stage(0, 0);
    load_stage(1, 1);
    load_stage(2, 2);
    int buf = 0;
    for (int kt = 0; kt < KT; ++kt) {
        if (kt + 3 < KT) {
            int nb = buf + 3; if (nb >= NSTAGE) nb -= NSTAGE;
            load_stage(kt + 3, nb);
            CP_WAIT(3);
        } else if (kt + 2 < KT) { CP_WAIT(2); }
        else if (kt + 1 < KT)   { CP_WAIT(1); }
        else                    { CP_WAIT(0); }
        __syncthreads();

        uint32_t base = sb + buf * STAGE_SZ;
        uint32_t a0[4][4], b0[4][2], a1[4][4], b1[4][2];
        load_frags(base, 0, a0, b0);
        load_frags(base, 1, a1, b1);
        do_mmas(a0, b0);
        do_mmas(a1, b1);
        __syncthreads();
        if (++buf == NSTAGE) buf = 0;
    }

    #pragma unroll
    for (int mt = 0; mt < 4; ++mt) {
        #pragma unroll
        for (int nj = 0; nj < 4; ++nj) {
            int row0 = bm + wm * 64 + mt * 16 + (lane >> 2);
            int col  = bn + wn * 32 + nj * 8 + (lane & 3) * 2;
            float b0 = bias[col], b1 = bias[col + 1];
            float v[4] = { c[mt][nj][0] + b0, c[mt][nj][1] + b1,
                           c[mt][nj][2] + b0, c[mt][nj][3] + b1 };
            if (EPI == EPI_SOFTPLUS) {
                #pragma unroll
                for (int r = 0; r < 4; ++r) {
                    float sp = fmaxf(v[r], 0.f) + log1pf(expf(-fabsf(v[r])));
                    v[r] = fminf(fmaxf(sp, 1e-4f), 10.0f);
                }
            } else if (EPI == EPI_RESID) {
                long p0 = (long)row0 * N + col, p1 = (long)(row0 + 8) * N + col;
                v[0] += resid[p0]; v[1] += resid[p0 + 1];
                v[2] += resid[p1]; v[3] += resid[p1 + 1];
            }
            *(float2*)(C + (long)row0 * N + col)       = make_float2(v[0], v[1]);
            *(float2*)(C + (long)(row0 + 8) * N + col) = make_float2(v[2], v[3]);
        }
    }
}

// ---------------------------------------------------------------------------
// Causal depthwise conv(4) + bias + SiLU; emits fp32 + bf16
// ---------------------------------------------------------------------------
__global__ void conv_silu_kernel(const float* __restrict__ conv_w,
                                 const float* __restrict__ conv_b) {
    int idx = blockIdx.x * blockDim.x + threadIdx.x;
    if (idx >= BATCH * LSEQ * DINNER) return;
    int c = idx & (DINNER - 1);
    int t = (idx >> 11) & (LSEQ - 1);
    int b = idx >> 21;
    const float* xin = g_xz + (long)(b * LSEQ) * (2 * DINNER) + c;
    float acc = conv_b[c];
    #pragma unroll
    for (int j = 0; j < DCONV; ++j) {
        int tt = t - (DCONV - 1) + j;
        if (tt >= 0) acc = fmaf(xin[(long)tt * (2 * DINNER)], conv_w[c * DCONV + j], acc);
    }
    float sig = 1.0f / (1.0f + expf(-acc));
    float yv = acc * sig;
    long o = (long)(b * LSEQ + t) * DINNER + c;
    g_xc[o] = yv;
    g_xc_h[o] = __float2bfloat16(yv);
}

// ---------------------------------------------------------------------------
// x_proj: BC = xc @ W[32,2048]^T + b, written INTERLEAVED: [row][s][{B,C}]
// ---------------------------------------------------------------------------
__global__ __launch_bounds__(256)
void xproj_kernel(const float* __restrict__ W, const float* __restrict__ bias) {
    __shared__ float Xs[32][65];
    __shared__ float Ws[32][65];
    int tid = threadIdx.x;
    int row0 = blockIdx.x * 32;
    int rg = (tid >> 5) * 4;
    int n  = tid & 31;
    float acc[4] = {0.f, 0.f, 0.f, 0.f};
    for (int k0 = 0; k0 < DINNER; k0 += 64) {
        #pragma unroll
        for (int i = 0; i < 2; ++i) {
            int id = tid * 2 + i;
            int r = id >> 4, c4 = (id & 15) * 4;
            float4 xv = *(const float4*)(g_xc + (long)(row0 + r) * DINNER + k0 + c4);
            Xs[r][c4] = xv.x; Xs[r][c4+1] = xv.y; Xs[r][c4+2] = xv.z; Xs[r][c4+3] = xv.w;
            float4 wv = *(const float4*)(W + (long)r * DINNER + k0 + c4);
            Ws[r][c4] = wv.x; Ws[r][c4+1] = wv.y; Ws[r][c4+2] = wv.z; Ws[r][c4+3] = wv.w;
        }
        __syncthreads();
        #pragma unroll
        for (int kk = 0; kk < 64; ++kk) {
            float w = Ws[n][kk];
            #pragma unroll
            for (int i = 0; i < 4; ++i) acc[i] = fmaf(Xs[rg + i][kk], w, acc[i]);
        }
        __syncthreads();
    }
    float bv = bias[n];
    int off = (n & 15) * 2 + (n >> 4);          // interleave B,C per state
    #pragma unroll
    for (int i = 0; i < 4; ++i)
        g_bc[(long)(row0 + rg + i) * 32 + off] = acc[i] + bv;
}

// ---------------------------------------------------------------------------
// Selective scan + z-gate.
// Warp = 8 channels x 4 lanes/channel; each lane holds 4 states in registers.
// B/C shared across channels (depend on (b,t) only) -> 2-shfl reductions.
// 4-deep register prefetch of all operands.
// ---------------------------------------------------------------------------
#define PFD 4
__global__ __launch_bounds__(128)
void scan_kernel(const float* __restrict__ A_log,
                 const float* __restrict__ Dvec) {
    int gw   = (blockIdx.x * blockDim.x + threadIdx.x) >> 5;   // 0..511
    int lane = threadIdx.x & 31;
    int chl  = lane >> 2;                    // channel within warp (0..7)
    int sg   = lane & 3;                     // state group
    int s0   = sg * 4;                       // states s0..s0+3
    int pair = gw * 8 + chl;                 // 0..4095 over (b, c)
    int b = pair >> 11;
    int c = pair & (DINNER - 1);

    float a[4], h[4] = {0.f, 0.f, 0.f, 0.f};
    #pragma unroll
    for (int k = 0; k < 4; ++k) a[k] = -expf(A_log[c * DSTATE + s0 + k]);
    float Dc = Dvec[c];

    const float* dl  = g_delta + (long)b * LSEQ * DINNER + c;
    const float* xcb = g_xc    + (long)b * LSEQ * DINNER + c;
    const float* bcb = g_bc    + (long)b * LSEQ * 32 + s0 * 2;   // [t][s][{B,C}]
    const float* zb  = g_xz    + (long)b * LSEQ * 2 * DINNER + DINNER + c;
    __nv_bfloat16* yb = g_y_h  + (long)b * LSEQ * DINNER + c;

    float  dbuf[PFD], xbuf[PFD], zbuf[PFD];
    float4 bc0buf[PFD], bc1buf[PFD];         // {B[s0],C[s0],B[s0+1],C[s0+1]}, {s0+2,s0+3}
    #pragma unroll
    for (int i = 0; i < PFD; ++i) {
        dbuf[i]   = dl [(long)i * DINNER];
        xbuf[i]   = xcb[(long)i * DINNER];
        bc0buf[i] = *(const float4*)(bcb + i * 32);
        bc1buf[i] = *(const float4*)(bcb + i * 32 + 4);
        zbuf[i]   = zb [(long)i * 2 * DINNER];
    }

    for (int t0 = 0; t0 < LSEQ; t0 += 16) {
        #pragma unroll
        for (int j = 0; j < 16; ++j) {
            int t = t0 + j;
            int slot = j & (PFD - 1);
            float  d   = dbuf[slot];
            float  xv  = xbuf[slot];
            float4 bc0 = bc0buf[slot];
            float4 bc1 = bc1buf[slot];
            float  z   = zbuf[slot];
            // refill with t+PFD (independent of everything below)
            int tn = t + PFD; if (tn >= LSEQ) tn = LSEQ - 1;
            dbuf[slot]   = dl [(long)tn * DINNER];
            xbuf[slot]   = xcb[(long)tn * DINNER];
            bc0buf[slot] = *(const float4*)(bcb + tn * 32);
            bc1buf[slot] = *(const float4*)(bcb + tn * 32 + 4);
            zbuf[slot]   = zb [(long)tn * 2 * DINNER];

            float dx = d * xv;
            float da0 = __expf(fmaxf(d * a[0], -10.f));
            float da1 = __expf(fmaxf(d * a[1], -10.f));
            float da2 = __expf(fmaxf(d * a[2], -10.f));
            float da3 = __expf(fmaxf(d * a[3], -10.f));
            h[0] = fmaf(da0, h[0], dx * bc0.x);
            h[1] = fmaf(da1, h[1], dx * bc0.z);
            h[2] = fmaf(da2, h[2], dx * bc1.x);
            h[3] = fmaf(da3, h[3], dx * bc1.z);
            if (j == 15) {
                float ss = h[0]*h[0] + h[1]*h[1] + h[2]*h[2] + h[3]*h[3];
                ss += __shfl_xor_sync(0xffffffffu, ss, 1);
                ss += __shfl_xor_sync(0xffffffffu, ss, 2);
                if (ss > 100.0f) {
                    float r = 10.0f * rsqrtf(ss);
                    h[0] *= r; h[1] *= r; h[2] *= r; h[3] *= r;
                }
            }
            float p = h[0]*bc0.y + h[1]*bc0.w + h[2]*bc1.y + h[3]*bc1.w;
            p += __shfl_xor_sync(0xffffffffu, p, 1);
            p += __shfl_xor_sync(0xffffffffu, p, 2);
            if (sg == 0) {
                float yv = p + Dc * xv;
                yv *= z / (1.0f + __expf(-z));
                yb[(long)t * DINNER] = __float2bfloat16(yv);
            }
        }
    }
}

// ---------------------------------------------------------------------------
// Launch (in_proj GEMM stays at capture index 3)
// ---------------------------------------------------------------------------
extern "C" void kernel_launch(void* const* d_in, const int* in_sizes, int n_in,
                              void* d_out, int out_size) {
    const float* x             = (const float*)d_in[0];
    const float* in_proj_w     = (const float*)d_in[1];
    const float* in_proj_b     = (const float*)d_in[2];
    const float* conv_w        = (const float*)d_in[3];
    const float* conv_b        = (const float*)d_in[4];
    const float* x_proj_w      = (const float*)d_in[5];
    const float* x_proj_b      = (const float*)d_in[6];
    const float* dt_proj_w     = (const float*)d_in[7];
    const float* dt_proj_b     = (const float*)d_in[8];
    const float* A_log         = (const float*)d_in[9];
    const float* Dvec          = (const float*)d_in[10];
    const float* out_proj_w    = (const float*)d_in[11];
    const float* out_proj_b    = (const float*)d_in[12];
    const float* in_norm_alpha = (const float*)d_in[13];
    const float* in_norm_bias  = (const float*)d_in[14];
    const float* norm_alpha    = (const float*)d_in[15];
    const float* norm_bias     = (const float*)d_in[16];
    float* out = (float*)d_out;

    __nv_bfloat16 *xn_h, *wi_h, *wd_h, *wo_h, *xc_h, *y_h;
    float *xz, *delta, *obuf;
    cudaGetSymbolAddress((void**)&xn_h, g_xn_h);
    cudaGetSymbolAddress((void**)&wi_h, g_wi_h);
    cudaGetSymbolAddress((void**)&wd_h, g_wd_h);
    cudaGetSymbolAddress((void**)&wo_h, g_wo_h);
    cudaGetSymbolAddress((void**)&xc_h, g_xc_h);
    cudaGetSymbolAddress((void**)&y_h,  g_y_h);
    cudaGetSymbolAddress((void**)&xz,    g_xz);
    cudaGetSymbolAddress((void**)&delta, g_delta);
    cudaGetSymbolAddress((void**)&obuf,  g_out);

    cudaFuncSetAttribute(gemm_hmma<EPI_BIAS>,     cudaFuncAttributeMaxDynamicSharedMemorySize, GEMM_SMEM);
    cudaFuncSetAttribute(gemm_hmma<EPI_SOFTPLUS>, cudaFuncAttributeMaxDynamicSharedMemorySize, GEMM_SMEM);
    cudaFuncSetAttribute(gemm_hmma<EPI_RESID>,    cudaFuncAttributeMaxDynamicSharedMemorySize, GEMM_SMEM);

    // 0. input layernorm -> bf16
    ln_kernel<1><<<ROWS, 256>>>(x, in_norm_alpha, in_norm_bias, nullptr, xn_h);
    // 1-2. weight converts for first two GEMMs
    cvt_kernel<<<(2 * DINNER * DMODEL / 4 + 255) / 256, 256>>>(in_proj_w, wi_h, 2 * DINNER * DMODEL / 4);
    cvt_kernel<<<(DINNER * DINNER / 4 + 255) / 256, 256>>>(dt_proj_w, wd_h, DINNER * DINNER / 4);
    // 3. in_proj (2048 x 4096 x 1024)  <-- ncu capture slot
    gemm_hmma<EPI_BIAS><<<dim3(32, 16), 256, GEMM_SMEM>>>(
        xn_h, wi_h, in_proj_b, nullptr, xz, ROWS, 2 * DINNER, DMODEL);
    // 4. conv + silu
    conv_silu_kernel<<<(BATCH * LSEQ * DINNER) / 256, 256>>>(conv_w, conv_b);
    // 5. x_proj -> interleaved B,C
    xproj_kernel<<<ROWS / 32, 256>>>(x_proj_w, x_proj_b);
    // 6. dt_proj + softplus + clip (2048 x 2048 x 2048)
    gemm_hmma<EPI_SOFTPLUS><<<dim3(16, 16), 256, GEMM_SMEM>>>(
        xc_h, wd_h, dt_proj_b, nullptr, delta, ROWS, DINNER, DINNER);
    // 7. selective scan + z gate (128 blocks x 4 warps; warp = 8 channels)
    scan_kernel<<<128, 128>>>(A_log, Dvec);
    // 8. out_proj weight convert
    cvt_kernel<<<(DMODEL * DINNER / 4 + 255) / 256, 256>>>(out_proj_w, wo_h, DMODEL * DINNER / 4);
    // 9. out_proj + residual (2048 x 1024 x 2048)
    gemm_hmma<EPI_RESID><<<dim3(8, 16), 256, GEMM_SMEM>>>(
        y_h, wo_h, out_proj_b, x, obuf, ROWS, DMODEL, DINNER);
    // 10. final layernorm -> d_out
    ln_kernel<0><<<ROWS, 256>>>(obuf, norm_alpha, norm_bias, out, nullptr);
}

// round 10
// speedup vs baseline: 5.2067x; 1.2946x over previous
#include <cuda_runtime.h>
#include <cuda_bf16.h>
#include <math.h>
#include <stdint.h>

// ---------------------------------------------------------------------------
// Shapes (fixed): B=2, L=1024, d_model=1024, d_state=16, d_conv=4, d_inner=2048
// ---------------------------------------------------------------------------
#define BATCH    2
#define LSEQ     1024
#define DMODEL   1024
#define DSTATE   16
#define DCONV    4
#define DINNER   2048
#define ROWS     (BATCH * LSEQ)
#define NSEG     64                       // 1024 / 16
#define SEGLEN   16

// ---------------------------------------------------------------------------
// Scratch (device globals; no allocation allowed)
// ---------------------------------------------------------------------------
__device__ __nv_bfloat16 g_xn_h[ROWS * DMODEL];
__device__ __nv_bfloat16 g_wi_h[2 * DINNER * DMODEL];
__device__ __nv_bfloat16 g_wd_h[DINNER * DINNER];
__device__ __nv_bfloat16 g_wo_h[DMODEL * DINNER];
__device__ __nv_bfloat16 g_xc_h[ROWS * DINNER];
__device__ __nv_bfloat16 g_y_h [ROWS * DINNER];
__device__ float g_xz   [ROWS * 2 * DINNER];
__device__ float g_xc   [ROWS * DINNER];
__device__ float g_bc   [ROWS * 2 * DSTATE];    // interleaved [t][s][{B,C}]
__device__ float g_delta[ROWS * DINNER];
__device__ float g_out  [ROWS * DMODEL];
// chunked-scan intermediates: [pair(=b*DINNER+c)][seg][state]
__device__ float g_ap[(long)BATCH * DINNER * NSEG * DSTATE];
__device__ float g_hd[(long)BATCH * DINNER * NSEG * DSTATE];
__device__ float g_hs[(long)BATCH * DINNER * NSEG * DSTATE];

// ---------------------------------------------------------------------------
// PTX helpers (plain sm_80+ features only)
// ---------------------------------------------------------------------------
__device__ __forceinline__ uint32_t smem_to_u32(const void* p) {
    uint32_t a;
    asm("{ .reg .u64 t; cvta.to.shared.u64 t, %1; cvt.u32.u64 %0, t; }" : "=r"(a) : "l"(p));
    return a;
}
#define CP_ASYNC16(dst, src) \
    asm volatile("cp.async.cg.shared.global [%0], [%1], 16;" :: "r"(dst), "l"(src))
#define CP_COMMIT() asm volatile("cp.async.commit_group;" ::: "memory")
#define CP_WAIT(n)  asm volatile("cp.async.wait_group %0;" :: "n"(n) : "memory")

__device__ __forceinline__ void ldsm_x4(uint32_t* r, uint32_t addr) {
    asm volatile("ldmatrix.sync.aligned.m8n8.x4.shared.b16 {%0,%1,%2,%3}, [%4];"
        : "=r"(r[0]), "=r"(r[1]), "=r"(r[2]), "=r"(r[3]) : "r"(addr));
}
__device__ __forceinline__ void mma_bf16(float* c, const uint32_t* a, const uint32_t* b) {
    asm volatile(
        "mma.sync.aligned.m16n8k16.row.col.f32.bf16.bf16.f32 "
        "{%0,%1,%2,%3}, {%4,%5,%6,%7}, {%8,%9}, {%0,%1,%2,%3};"
        : "+f"(c[0]), "+f"(c[1]), "+f"(c[2]), "+f"(c[3])
        : "r"(a[0]), "r"(a[1]), "r"(a[2]), "r"(a[3]), "r"(b[0]), "r"(b[1]));
}

// ---------------------------------------------------------------------------
// LayerNorm (ddof=1 std, eps on std). SPLIT=1 emits bf16, else fp32.
// ---------------------------------------------------------------------------
__device__ __forceinline__ float warp_sum32(float v) {
    #pragma unroll
    for (int m = 16; m > 0; m >>= 1) v += __shfl_xor_sync(0xffffffffu, v, m);
    return v;
}

template<int SPLIT>
__global__ void ln_kernel(const float* __restrict__ X,
                          const float* __restrict__ alpha,
                          const float* __restrict__ beta,
                          float* __restrict__ Y,
                          __nv_bfloat16* __restrict__ Yh) {
    __shared__ float sh[2][8];
    int row = blockIdx.x;
    int tid = threadIdx.x;
    const float* xr = X + (long)row * DMODEL;
    float4 xv = *(const float4*)(xr + tid * 4);
    float s  = xv.x + xv.y + xv.z + xv.w;
    float ss = xv.x*xv.x + xv.y*xv.y + xv.z*xv.z + xv.w*xv.w;
    s = warp_sum32(s); ss = warp_sum32(ss);
    if ((tid & 31) == 0) { sh[0][tid >> 5] = s; sh[1][tid >> 5] = ss; }
    __syncthreads();
    float S = 0.f, SS = 0.f;
    #pragma unroll
    for (int w = 0; w < 8; ++w) { S += sh[0][w]; SS += sh[1][w]; }
    float mean = S * (1.0f / (float)DMODEL);
    float var  = fmaxf((SS - (float)DMODEL * mean * mean) * (1.0f / (float)(DMODEL - 1)), 0.f);
    float inv  = 1.0f / (sqrtf(var) + 1e-6f);
    float4 av = *(const float4*)(alpha + tid * 4);
    float4 bv = *(const float4*)(beta  + tid * 4);
    float o[4];
    o[0] = av.x * (xv.x - mean) * inv + bv.x;
    o[1] = av.y * (xv.y - mean) * inv + bv.y;
    o[2] = av.z * (xv.z - mean) * inv + bv.z;
    o[3] = av.w * (xv.w - mean) * inv + bv.w;
    long base = (long)row * DMODEL + tid * 4;
    if (SPLIT) {
        __nv_bfloat16 h[4];
        #pragma unroll
        for (int j = 0; j < 4; ++j) h[j] = __float2bfloat16(o[j]);
        *(uint2*)(Yh + base) = *(uint2*)h;
    } else {
        *(float4*)(Y + base) = make_float4(o[0], o[1], o[2], o[3]);
    }
}

// ---------------------------------------------------------------------------
// fp32 -> bf16 convert (weights)
// ---------------------------------------------------------------------------
__global__ void cvt_kernel(const float* __restrict__ X,
                           __nv_bfloat16* __restrict__ H, int n4) {
    int i = blockIdx.x * blockDim.x + threadIdx.x;
    if (i >= n4) return;
    float4 v = *(const float4*)(X + (long)i * 4);
    __nv_bfloat16 h[4] = { __float2bfloat16(v.x), __float2bfloat16(v.y),
                           __float2bfloat16(v.z), __float2bfloat16(v.w) };
    *(uint2*)(H + (long)i * 4) = *(uint2*)h;
}

// ---------------------------------------------------------------------------
// Single-pass bf16 HMMA GEMM (4-stage cp.async, 2 CTA/SM)
// ---------------------------------------------------------------------------
#define EPI_BIAS     0
#define EPI_SOFTPLUS 1
#define EPI_RESID    2
#define ROWB      80
#define ARR_SZ    (128 * ROWB)
#define STAGE_SZ  (2 * ARR_SZ)
#define NSTAGE    4
#define GEMM_SMEM (NSTAGE * STAGE_SZ)

template<int EPI>
__global__ __launch_bounds__(256, 2)
void gemm_hmma(const __nv_bfloat16* __restrict__ A, const __nv_bfloat16* __restrict__ B,
               const float* __restrict__ bias, const float* __restrict__ resid,
               float* __restrict__ C, int M, int N, int K) {
    extern __shared__ char smem[];
    uint32_t sb = smem_to_u32(smem);
    int tid  = threadIdx.x;
    int lane = tid & 31;
    int wid  = tid >> 5;
    int wm   = wid & 1;
    int wn   = wid >> 1;
    int bm = blockIdx.y * 128, bn = blockIdx.x * 128;

    const __nv_bfloat16* srcs[2] = { A + (long)bm * K, B + (long)bn * K };

    int s_arr[4], s_row[4], s_c[4];
    #pragma unroll
    for (int i = 0; i < 4; ++i) {
        int id = tid + i * 256;
        s_arr[i] = id >> 9;
        int rem = id & 511;
        s_row[i] = rem >> 2;
        s_c[i]   = rem & 3;
    }

    auto load_stage = [&](int kt, int buf) {
        #pragma unroll
        for (int i = 0; i < 4; ++i) {
            uint32_t dst = sb + buf * STAGE_SZ + s_arr[i] * ARR_SZ
                         + s_row[i] * ROWB + s_c[i] * 16;
            const __nv_bfloat16* src = srcs[s_arr[i]] + (long)s_row[i] * K
                                     + kt * 32 + s_c[i] * 8;
            CP_ASYNC16(dst, src);
        }
        CP_COMMIT();
    };

    float c[4][4][4];
    #pragma unroll
    for (int mt = 0; mt < 4; ++mt)
        #pragma unroll
        for (int nj = 0; nj < 4; ++nj)
            #pragma unroll
            for (int r = 0; r < 4; ++r) c[mt][nj][r] = 0.f;

    int a_row = wm * 64 + (lane & 15);
    int a_kb  = (lane >> 4) << 4;
    int b_row = wn * 32 + ((lane >> 4) << 3) + (lane & 7);
    int b_kb  = ((lane >> 3) & 1) << 4;

    auto load_frags = [&](uint32_t base, int ks, uint32_t a[4][4], uint32_t b[4][2]) {
        uint32_t kboff = ks * 32;
        #pragma unroll
        for (int mt = 0; mt < 4; ++mt) {
            uint32_t off = (uint32_t)((a_row + mt * 16) * ROWB) + a_kb + kboff;
            ldsm_x4(a[mt], base + off);
        }
        #pragma unroll
        for (int nt = 0; nt < 2; ++nt) {
            uint32_t off = (uint32_t)((b_row + nt * 16) * ROWB) + b_kb + kboff;
            uint32_t t0[4];
            ldsm_x4(t0, base + ARR_SZ + off);
            b[nt*2][0]   = t0[0]; b[nt*2][1]   = t0[1];
            b[nt*2+1][0] = t0[2]; b[nt*2+1][1] = t0[3];
        }
    };
    auto do_mmas = [&](uint32_t a[4][4], uint32_t b[4][2]) {
        #pragma unroll
        for (int mt = 0; mt < 4; ++mt)
            #pragma unroll
            for (int nj = 0; nj < 4; ++nj)
                mma_bf16(c[mt][nj], a[mt], b[nj]);
    };

    const int KT = K >> 5;
    load_stage(0, 0);
    load_stage(1, 1);
    load_stage(2, 2);
    int buf = 0;
    for (int kt = 0; kt < KT; ++kt) {
        if (kt + 3 < KT) {
            int nb = buf + 3; if (nb >= NSTAGE) nb -= NSTAGE;
            load_stage(kt + 3, nb);
            CP_WAIT(3);
        } else if (kt + 2 < KT) { CP_WAIT(2); }
        else if (kt + 1 < KT)   { CP_WAIT(1); }
        else                    { CP_WAIT(0); }
        __syncthreads();

        uint32_t base = sb + buf * STAGE_SZ;
        uint32_t a0[4][4], b0[4][2], a1[4][4], b1[4][2];
        load_frags(base, 0, a0, b0);
        load_frags(base, 1, a1, b1);
        do_mmas(a0, b0);
        do_mmas(a1, b1);
        __syncthreads();
        if (++buf == NSTAGE) buf = 0;
    }

    #pragma unroll
    for (int mt = 0; mt < 4; ++mt) {
        #pragma unroll
        for (int nj = 0; nj < 4; ++nj) {
            int row0 = bm + wm * 64 + mt * 16 + (lane >> 2);
            int col  = bn + wn * 32 + nj * 8 + (lane & 3) * 2;
            float b0 = bias[col], b1 = bias[col + 1];
            float v[4] = { c[mt][nj][0] + b0, c[mt][nj][1] + b1,
                           c[mt][nj][2] + b0, c[mt][nj][3] + b1 };
            if (EPI == EPI_SOFTPLUS) {
                #pragma unroll
                for (int r = 0; r < 4; ++r) {
                    float sp = fmaxf(v[r], 0.f) + log1pf(expf(-fabsf(v[r])));
                    v[r] = fminf(fmaxf(sp, 1e-4f), 10.0f);
                }
            } else if (EPI == EPI_RESID) {
                long p0 = (long)row0 * N + col, p1 = (long)(row0 + 8) * N + col;
                v[0] += resid[p0]; v[1] += resid[p0 + 1];
                v[2] += resid[p1]; v[3] += resid[p1 + 1];
            }
            *(float2*)(C + (long)row0 * N + col)       = make_float2(v[0], v[1]);
            *(float2*)(C + (long)(row0 + 8) * N + col) = make_float2(v[2], v[3]);
        }
    }
}

// ---------------------------------------------------------------------------
// Causal depthwise conv(4) + bias + SiLU; emits fp32 + bf16
// ---------------------------------------------------------------------------
__global__ void conv_silu_kernel(const float* __restrict__ conv_w,
                                 const float* __restrict__ conv_b) {
    int idx = blockIdx.x * blockDim.x + threadIdx.x;
    if (idx >= BATCH * LSEQ * DINNER) return;
    int c = idx & (DINNER - 1);
    int t = (idx >> 11) & (LSEQ - 1);
    int b = idx >> 21;
    const float* xin = g_xz + (long)(b * LSEQ) * (2 * DINNER) + c;
    float acc = conv_b[c];
    #pragma unroll
    for (int j = 0; j < DCONV; ++j) {
        int tt = t - (DCONV - 1) + j;
        if (tt >= 0) acc = fmaf(xin[(long)tt * (2 * DINNER)], conv_w[c * DCONV + j], acc);
    }
    float sig = 1.0f / (1.0f + expf(-acc));
    float yv = acc * sig;
    long o = (long)(b * LSEQ + t) * DINNER + c;
    g_xc[o] = yv;
    g_xc_h[o] = __float2bfloat16(yv);
}

// ---------------------------------------------------------------------------
// x_proj: BC = xc @ W[32,2048]^T + b, written INTERLEAVED: [row][s][{B,C}]
// ---------------------------------------------------------------------------
__global__ __launch_bounds__(256)
void xproj_kernel(const float* __restrict__ W, const float* __restrict__ bias) {
    __shared__ float Xs[32][65];
    __shared__ float Ws[32][65];
    int tid = threadIdx.x;
    int row0 = blockIdx.x * 32;
    int rg = (tid >> 5) * 4;
    int n  = tid & 31;
    float acc[4] = {0.f, 0.f, 0.f, 0.f};
    for (int k0 = 0; k0 < DINNER; k0 += 64) {
        #pragma unroll
        for (int i = 0; i < 2; ++i) {
            int id = tid * 2 + i;
            int r = id >> 4, c4 = (id & 15) * 4;
            float4 xv = *(const float4*)(g_xc + (long)(row0 + r) * DINNER + k0 + c4);
            Xs[r][c4] = xv.x; Xs[r][c4+1] = xv.y; Xs[r][c4+2] = xv.z; Xs[r][c4+3] = xv.w;
            float4 wv = *(const float4*)(W + (long)r * DINNER + k0 + c4);
            Ws[r][c4] = wv.x; Ws[r][c4+1] = wv.y; Ws[r][c4+2] = wv.z; Ws[r][c4+3] = wv.w;
        }
        __syncthreads();
        #pragma unroll
        for (int kk = 0; kk < 64; ++kk) {
            float w = Ws[n][kk];
            #pragma unroll
            for (int i = 0; i < 4; ++i) acc[i] = fmaf(Xs[rg + i][kk], w, acc[i]);
        }
        __syncthreads();
    }
    float bv = bias[n];
    int off = (n & 15) * 2 + (n >> 4);          // interleave B,C per state
    #pragma unroll
    for (int i = 0; i < 4; ++i)
        g_bc[(long)(row0 + rg + i) * 32 + off] = acc[i] + bv;
}

// ---------------------------------------------------------------------------
// Chunked selective scan.
// Phase 1: per-segment transfer (A_g = prod dA) and driven response (hd) from
//          h=0. Warp = 8 channels x 4 lanes x 4 states; one segment per warp.
// Phase 2: 64-step serial propagation of segment-start states + renorm.
//          Warp = 2 channels x 16 lanes (states).
// Phase 3: re-run each segment from its true start state; renorm at j=15;
//          emit gated y. Same layout as phase 1.
// ---------------------------------------------------------------------------
__global__ __launch_bounds__(256)
void scan_p1(const float* __restrict__ A_log) {
    int gw   = (blockIdx.x * blockDim.x + threadIdx.x) >> 5;   // 0..32767
    int lane = threadIdx.x & 31;
    int chl  = lane >> 2;
    int sg   = lane & 3;
    int s0   = sg * 4;
    int seg  = gw & (NSEG - 1);
    int pair = (gw >> 6) * 8 + chl;
    int b = pair >> 11;
    int c = pair & (DINNER - 1);

    float a[4];
    #pragma unroll
    for (int k = 0; k < 4; ++k) a[k] = -expf(A_log[c * DSTATE + s0 + k]);

    const float* dl  = g_delta + (long)b * LSEQ * DINNER + c;
    const float* xcb = g_xc    + (long)b * LSEQ * DINNER + c;
    const float* bcb = g_bc    + (long)b * LSEQ * 32 + s0 * 2;

    float h[4] = {0.f, 0.f, 0.f, 0.f};
    float ap[4] = {1.f, 1.f, 1.f, 1.f};
    int tb = seg * SEGLEN;
    #pragma unroll
    for (int j = 0; j < SEGLEN; ++j) {
        int t = tb + j;
        float  d   = dl [(long)t * DINNER];
        float  xv  = xcb[(long)t * DINNER];
        float4 bc0 = *(const float4*)(bcb + t * 32);
        float4 bc1 = *(const float4*)(bcb + t * 32 + 4);
        float dx = d * xv;
        float da0 = __expf(fmaxf(d * a[0], -10.f));
        float da1 = __expf(fmaxf(d * a[1], -10.f));
        float da2 = __expf(fmaxf(d * a[2], -10.f));
        float da3 = __expf(fmaxf(d * a[3], -10.f));
        h[0] = fmaf(da0, h[0], dx * bc0.x);  ap[0] *= da0;
        h[1] = fmaf(da1, h[1], dx * bc0.z);  ap[1] *= da1;
        h[2] = fmaf(da2, h[2], dx * bc1.x);  ap[2] *= da2;
        h[3] = fmaf(da3, h[3], dx * bc1.z);  ap[3] *= da3;
    }
    long base = ((long)pair * NSEG + seg) * DSTATE + s0;
    *(float4*)(g_hd + base) = make_float4(h[0], h[1], h[2], h[3]);
    *(float4*)(g_ap + base) = make_float4(ap[0], ap[1], ap[2], ap[3]);
}

__global__ __launch_bounds__(256)
void scan_p2() {
    int gw   = (blockIdx.x * blockDim.x + threadIdx.x) >> 5;   // 0..2047
    int lane = threadIdx.x & 31;
    int s    = lane & 15;
    int half = lane >> 4;
    int pair = gw * 2 + half;

    float h = 0.f;
    long base = (long)pair * NSEG * DSTATE + s;
    for (int g = 0; g < NSEG; ++g) {
        long idx = base + (long)g * DSTATE;
        g_hs[idx] = h;                      // segment-start state for phase 3
        float ap = g_ap[idx];
        float hd = g_hd[idx];
        h = fmaf(ap, h, hd);
        float ss = h * h;
        ss += __shfl_xor_sync(0xffffffffu, ss, 8);
        ss += __shfl_xor_sync(0xffffffffu, ss, 4);
        ss += __shfl_xor_sync(0xffffffffu, ss, 2);
        ss += __shfl_xor_sync(0xffffffffu, ss, 1);
        if (ss > 100.0f) h *= 10.0f * rsqrtf(ss);
    }
}

__global__ __launch_bounds__(256)
void scan_p3(const float* __restrict__ A_log, const float* __restrict__ Dvec) {
    int gw   = (blockIdx.x * blockDim.x + threadIdx.x) >> 5;   // 0..32767
    int lane = threadIdx.x & 31;
    int chl  = lane >> 2;
    int sg   = lane & 3;
    int s0   = sg * 4;
    int seg  = gw & (NSEG - 1);
    int pair = (gw >> 6) * 8 + chl;
    int b = pair >> 11;
    int c = pair & (DINNER - 1);

    float a[4];
    #pragma unroll
    for (int k = 0; k < 4; ++k) a[k] = -expf(A_log[c * DSTATE + s0 + k]);
    float Dc = Dvec[c];

    const float* dl  = g_delta + (long)b * LSEQ * DINNER + c;
    const float* xcb = g_xc    + (long)b * LSEQ * DINNER + c;
    const float* bcb = g_bc    + (long)b * LSEQ * 32 + s0 * 2;
    const float* zb  = g_xz    + (long)b * LSEQ * 2 * DINNER + DINNER + c;
    __nv_bfloat16* yb = g_y_h  + (long)b * LSEQ * DINNER + c;

    float4 hs = *(const float4*)(g_hs + ((long)pair * NSEG + seg) * DSTATE + s0);
    float h[4] = { hs.x, hs.y, hs.z, hs.w };

    int tb = seg * SEGLEN;
    #pragma unroll
    for (int j = 0; j < SEGLEN; ++j) {
        int t = tb + j;
        float  d   = dl [(long)t * DINNER];
        float  xv  = xcb[(long)t * DINNER];
        float4 bc0 = *(const float4*)(bcb + t * 32);
        float4 bc1 = *(const float4*)(bcb + t * 32 + 4);
        float  z   = zb [(long)t * 2 * DINNER];
        float dx = d * xv;
        float da0 = __expf(fmaxf(d * a[0], -10.f));
        float da1 = __expf(fmaxf(d * a[1], -10.f));
        float da2 = __expf(fmaxf(d * a[2], -10.f));
        float da3 = __expf(fmaxf(d * a[3], -10.f));
        h[0] = fmaf(da0, h[0], dx * bc0.x);
        h[1] = fmaf(da1, h[1], dx * bc0.z);
        h[2] = fmaf(da2, h[2], dx * bc1.x);
        h[3] = fmaf(da3, h[3], dx * bc1.z);
        if (j == SEGLEN - 1) {
            float ss = h[0]*h[0] + h[1]*h[1] + h[2]*h[2] + h[3]*h[3];
            ss += __shfl_xor_sync(0xffffffffu, ss, 1);
            ss += __shfl_xor_sync(0xffffffffu, ss, 2);
            if (ss > 100.0f) {
                float r = 10.0f * rsqrtf(ss);
                h[0] *= r; h[1] *= r; h[2] *= r; h[3] *= r;
            }
        }
        float p = h[0]*bc0.y + h[1]*bc0.w + h[2]*bc1.y + h[3]*bc1.w;
        p += __shfl_xor_sync(0xffffffffu, p, 1);
        p += __shfl_xor_sync(0xffffffffu, p, 2);
        if (sg == 0) {
            float yv = p + Dc * xv;
            yv *= z / (1.0f + __expf(-z));
            yb[(long)t * DINNER] = __float2bfloat16(yv);
        }
    }
}

// ---------------------------------------------------------------------------
// Launch (in_proj GEMM stays at capture index 3)
// ---------------------------------------------------------------------------
extern "C" void kernel_launch(void* const* d_in, const int* in_sizes, int n_in,
                              void* d_out, int out_size) {
    const float* x             = (const float*)d_in[0];
    const float* in_proj_w     = (const float*)d_in[1];
    const float* in_proj_b     = (const float*)d_in[2];
    const float* conv_w        = (const float*)d_in[3];
    const float* conv_b        = (const float*)d_in[4];
    const float* x_proj_w      = (const float*)d_in[5];
    const float* x_proj_b      = (const float*)d_in[6];
    const float* dt_proj_w     = (const float*)d_in[7];
    const float* dt_proj_b     = (const float*)d_in[8];
    const float* A_log         = (const float*)d_in[9];
    const float* Dvec          = (const float*)d_in[10];
    const float* out_proj_w    = (const float*)d_in[11];
    const float* out_proj_b    = (const float*)d_in[12];
    const float* in_norm_alpha = (const float*)d_in[13];
    const float* in_norm_bias  = (const float*)d_in[14];
    const float* norm_alpha    = (const float*)d_in[15];
    const float* norm_bias     = (const float*)d_in[16];
    float* out = (float*)d_out;

    __nv_bfloat16 *xn_h, *wi_h, *wd_h, *wo_h, *xc_h, *y_h;
    float *xz, *delta, *obuf;
    cudaGetSymbolAddress((void**)&xn_h, g_xn_h);
    cudaGetSymbolAddress((void**)&wi_h, g_wi_h);
    cudaGetSymbolAddress((void**)&wd_h, g_wd_h);
    cudaGetSymbolAddress((void**)&wo_h, g_wo_h);
    cudaGetSymbolAddress((void**)&xc_h, g_xc_h);
    cudaGetSymbolAddress((void**)&y_h,  g_y_h);
    cudaGetSymbolAddress((void**)&xz,    g_xz);
    cudaGetSymbolAddress((void**)&delta, g_delta);
    cudaGetSymbolAddress((void**)&obuf,  g_out);

    cudaFuncSetAttribute(gemm_hmma<EPI_BIAS>,     cudaFuncAttributeMaxDynamicSharedMemorySize, GEMM_SMEM);
    cudaFuncSetAttribute(gemm_hmma<EPI_SOFTPLUS>, cudaFuncAttributeMaxDynamicSharedMemorySize, GEMM_SMEM);
    cudaFuncSetAttribute(gemm_hmma<EPI_RESID>,    cudaFuncAttributeMaxDynamicSharedMemorySize, GEMM_SMEM);

    // 0. input layernorm -> bf16
    ln_kernel<1><<<ROWS, 256>>>(x, in_norm_alpha, in_norm_bias, nullptr, xn_h);
    // 1-2. weight converts for first two GEMMs
    cvt_kernel<<<(2 * DINNER * DMODEL / 4 + 255) / 256, 256>>>(in_proj_w, wi_h, 2 * DINNER * DMODEL / 4);
    cvt_kernel<<<(DINNER * DINNER / 4 + 255) / 256, 256>>>(dt_proj_w, wd_h, DINNER * DINNER / 4);
    // 3. in_proj (2048 x 4096 x 1024)  <-- ncu capture slot
    gemm_hmma<EPI_BIAS><<<dim3(32, 16), 256, GEMM_SMEM>>>(
        xn_h, wi_h, in_proj_b, nullptr, xz, ROWS, 2 * DINNER, DMODEL);
    // 4. conv + silu
    conv_silu_kernel<<<(BATCH * LSEQ * DINNER) / 256, 256>>>(conv_w, conv_b);
    // 5. x_proj -> interleaved B,C
    xproj_kernel<<<ROWS / 32, 256>>>(x_proj_w, x_proj_b);
    // 6. dt_proj + softplus + clip (2048 x 2048 x 2048)
    gemm_hmma<EPI_SOFTPLUS><<<dim3(16, 16), 256, GEMM_SMEM>>>(
        xc_h, wd_h, dt_proj_b, nullptr, delta, ROWS, DINNER, DINNER);
    // 7. chunked selective scan (3 phases)
    scan_p1<<<4096, 256>>>(A_log);          // 32768 warps: per-segment A,hd
    scan_p2<<<256, 256>>>();                // 2048 warps: 64-step propagation
    scan_p3<<<4096, 256>>>(A_log, Dvec);    // 32768 warps: final y
    // 8. out_proj weight convert
    cvt_kernel<<<(DMODEL * DINNER / 4 + 255) / 256, 256>>>(out_proj_w, wo_h, DMODEL * DINNER / 4);
    // 9. out_proj + residual (2048 x 1024 x 2048)
    gemm_hmma<EPI_RESID><<<dim3(8, 16), 256, GEMM_SMEM>>>(
        y_h, wo_h, out_proj_b, x, obuf, ROWS, DMODEL, DINNER);
    // 10. final layernorm -> d_out
    ln_kernel<0><<<ROWS, 256>>>(obuf, norm_alpha, norm_bias, out, nullptr);
}